// round 9
// baseline (speedup 1.0000x reference)
#include <cuda_runtime.h>
#include <cuda_bf16.h>
#include <cstdint>

// Problem constants
#define BATCH   16
#define NQ      1024
#define NK      1024
#define DIN     512
#define NHEADS  8
#define HDIM    64
#define BN_TOT  (BATCH * NQ)       // 16384
#define NORM_F  0.125f             // 1/sqrt(64)
#define LOG2E   1.4426950408889634f

// -------- scratch (device globals: allocation-free) --------
__device__ float g_Q[(size_t)NHEADS * BN_TOT * HDIM];   // [h][bn][64]
__device__ float g_K[(size_t)NHEADS * BN_TOT * HDIM];
__device__ float g_V[(size_t)NHEADS * BN_TOT * HDIM];
__device__ float g_H[(size_t)BN_TOT * DIN];             // [bn][h*64+v]
__device__ unsigned long long g_Mb[(size_t)BN_TOT * (NK / 64)];  // packed mask bits

__device__ __forceinline__ float f2tf32_rna(float x) {
    uint32_t r;
    asm("cvt.rna.tf32.f32 %0, %1;" : "=r"(r) : "f"(x));
    return __uint_as_float(r);
}

// m16n8k8 tf32 mma (g=lane>>2, t=lane&3):
//   A: a0(g,t) a1(g+8,t) a2(g,t+4) a3(g+8,t+4)
//   B: b0(k=t,n=g) b1(k=t+4,n=g)
//   C: c0(g,2t) c1(g,2t+1) c2(g+8,2t) c3(g+8,2t+1)
__device__ __forceinline__ void mma_tf32(float* c, const uint32_t* a, const uint32_t* b) {
    asm volatile(
        "mma.sync.aligned.m16n8k8.row.col.f32.tf32.tf32.f32 "
        "{%0,%1,%2,%3}, {%4,%5,%6,%7}, {%8,%9}, {%0,%1,%2,%3};"
        : "+f"(c[0]), "+f"(c[1]), "+f"(c[2]), "+f"(c[3])
        : "r"(a[0]), "r"(a[1]), "r"(a[2]), "r"(a[3]), "r"(b[0]), "r"(b[1]));
}

// ============================================================
// Fused QKV projection, exact fp32 SIMT (R7 version — measured best).
// 128x128 tile, 256 threads, 8x8 microtile, BK=16, smem double-buffered.
// grid = (128 m-tiles, 4 n-tiles, 3 ops)
// ============================================================
#define QBM 128
#define QBN 128
#define QBK 16

__global__ __launch_bounds__(256)
void qkv_proj2(const float* __restrict__ q,
               const float* __restrict__ k,
               const float* __restrict__ v,
               const float* __restrict__ Wq,
               const float* __restrict__ Wk,
               const float* __restrict__ Wv)
{
    __shared__ float Xs[2][QBK][QBM];
    __shared__ float Ws[2][QBK][QBN];

    const int tid = threadIdx.x;
    const int tx  = tid & 15;
    const int ty  = tid >> 4;
    const int op  = blockIdx.z;
    const int m0  = blockIdx.x * QBM;
    const int n0  = blockIdx.y * QBN;

    const float* X = (op == 0 ? q : (op == 1 ? k : v));
    const float* W = (op == 0 ? Wq : (op == 1 ? Wk : Wv));
    float* Cb      = (op == 0 ? g_Q : (op == 1 ? g_K : g_V));

    const int mA  = tid & 127;
    const int k4a = tid >> 7;
    const float* Ag = X + (size_t)(m0 + mA) * DIN;
    const int kkB = tid >> 5;
    const int c4  = tid & 31;
    const float* Bg = W + (size_t)((n0 + c4 * 4) >> 6) * (DIN * HDIM)
                        + ((n0 + c4 * 4) & 63);

    float acc[8][8];
#pragma unroll
    for (int i = 0; i < 8; i++)
#pragma unroll
        for (int j = 0; j < 8; j++) acc[i][j] = 0.f;

    float4 ar[2], br[2];
#pragma unroll
    for (int i = 0; i < 2; ++i) {
        ar[i] = *(const float4*)(Ag + (k4a + 2 * i) * 4);
        br[i] = *(const float4*)(Bg + (size_t)(kkB + 8 * i) * HDIM);
    }
#pragma unroll
    for (int i = 0; i < 2; ++i) {
        int kr = (k4a + 2 * i) * 4;
        Xs[0][kr + 0][mA] = ar[i].x;
        Xs[0][kr + 1][mA] = ar[i].y;
        Xs[0][kr + 2][mA] = ar[i].z;
        Xs[0][kr + 3][mA] = ar[i].w;
        *(float4*)(&Ws[0][kkB + 8 * i][c4 * 4]) = br[i];
    }
    __syncthreads();

    for (int c = 0; c < DIN / QBK; ++c) {
        const int cur = c & 1;
        if (c < DIN / QBK - 1) {
            const int k0n = (c + 1) * QBK;
#pragma unroll
            for (int i = 0; i < 2; ++i) {
                ar[i] = *(const float4*)(Ag + k0n + (k4a + 2 * i) * 4);
                br[i] = *(const float4*)(Bg + (size_t)(k0n + kkB + 8 * i) * HDIM);
            }
        }

#pragma unroll
        for (int kk = 0; kk < QBK; ++kk) {
            float a[8], b[8];
            *(float4*)(a)     = *(const float4*)(&Xs[cur][kk][ty * 8]);
            *(float4*)(a + 4) = *(const float4*)(&Xs[cur][kk][ty * 8 + 4]);
            *(float4*)(b)     = *(const float4*)(&Ws[cur][kk][tx * 8]);
            *(float4*)(b + 4) = *(const float4*)(&Ws[cur][kk][tx * 8 + 4]);
#pragma unroll
            for (int i = 0; i < 8; i++)
#pragma unroll
                for (int j = 0; j < 8; j++)
                    acc[i][j] = fmaf(a[i], b[j], acc[i][j]);
        }

        if (c < DIN / QBK - 1) {
            const int nxt = cur ^ 1;
#pragma unroll
            for (int i = 0; i < 2; ++i) {
                int kr = (k4a + 2 * i) * 4;
                Xs[nxt][kr + 0][mA] = ar[i].x;
                Xs[nxt][kr + 1][mA] = ar[i].y;
                Xs[nxt][kr + 2][mA] = ar[i].z;
                Xs[nxt][kr + 3][mA] = ar[i].w;
                *(float4*)(&Ws[nxt][kkB + 8 * i][c4 * 4]) = br[i];
            }
            __syncthreads();
        }
    }

    const int cgl = n0 + tx * 8;
    const int h   = cgl >> 6;
    const int nh  = cgl & 63;
    float* Crow = Cb + (size_t)h * BN_TOT * HDIM
                     + (size_t)(m0 + ty * 8) * HDIM + nh;
#pragma unroll
    for (int i = 0; i < 8; i++) {
        *(float4*)(Crow + (size_t)i * HDIM)     =
            make_float4(acc[i][0], acc[i][1], acc[i][2], acc[i][3]);
        *(float4*)(Crow + (size_t)i * HDIM + 4) =
            make_float4(acc[i][4], acc[i][5], acc[i][6], acc[i][7]);
    }
}

// ============================================================
// Mask pack: 64 int32 -> 1 uint64 bitmask per (bq, key-tile) via ballot.
// ============================================================
__global__ __launch_bounds__(256)
void pack_mask(const int* __restrict__ mask)
{
    int w = (blockIdx.x * 256 + threadIdx.x) >> 5;
    int lane = threadIdx.x & 31;
    const int* src = mask + (size_t)w * 64;
    unsigned lo = __ballot_sync(0xffffffffu, src[lane] != 0);
    unsigned hi = __ballot_sync(0xffffffffu, src[lane + 32] != 0);
    if (lane == 0)
        g_Mb[w] = ((unsigned long long)hi << 32) | (unsigned long long)lo;
}

// ============================================================
// Out projection with RAW mma.sync (attn-style; wmma abstraction removed).
// C[16384,512] = H[16384,512] @ Wo[512,512] (Wo row-major [k][e]).
// Block 256 thr / 8 warps (4M x 2N); per warp 32x64 via m16n8k8 frags
// (2 m-frags x 8 n-frags, acc in 64 regs). BK=32, single-buffered smem
// (37.4 KB static -> 2 CTAs/SM), global prefetch into regs, 2 syncs/chunk.
// grid = (128 m-tiles, 4 n-tiles)
// ============================================================
#define OP_LDH 40    // 32 + 8
#define OP_LDW 136   // 128 + 8

__global__ __launch_bounds__(256, 2)
void out_proj3(const float* __restrict__ A,
               const float* __restrict__ B,
               float* __restrict__ C)
{
    __shared__ float sH[128 * OP_LDH];   // 20.0 KB
    __shared__ float sW[32 * OP_LDW];    // 17.4 KB

    const int tid  = threadIdx.x;
    const int w    = tid >> 5;
    const int lane = tid & 31;
    const int g    = lane >> 2;
    const int t    = lane & 3;
    const int wm   = w & 3;     // 4 warps in M (32 rows)
    const int wn   = w >> 2;    // 2 warps in N (64 cols)
    const int m0   = blockIdx.x * 128;
    const int n0   = blockIdx.y * 128;

    const float* At = A + (size_t)m0 * DIN;
    const float* Bt = B + n0;

    // staging patterns (1024 float4 each; 4 per thread)
    // H: idx = tid + i*256 -> m = idx>>3, c4 = idx&7
    // W: kk = (tid>>5) + i*8, c4b = tid&31
    const int c4b = tid & 31;

    float acc[2][8][4];
#pragma unroll
    for (int mi = 0; mi < 2; ++mi)
#pragma unroll
        for (int nf = 0; nf < 8; ++nf)
#pragma unroll
            for (int j = 0; j < 4; ++j) acc[mi][nf][j] = 0.f;

    float4 ar[4], br[4];
    // prologue: stage chunk 0
#pragma unroll
    for (int i = 0; i < 4; ++i) {
        int idx = tid + i * 256;
        ar[i] = *(const float4*)(At + (size_t)(idx >> 3) * DIN + (idx & 7) * 4);
        br[i] = *(const float4*)(Bt + (size_t)((tid >> 5) + i * 8) * DIN + c4b * 4);
    }
#pragma unroll
    for (int i = 0; i < 4; ++i) {
        int idx = tid + i * 256;
        float4 xv = ar[i];
        xv.x = f2tf32_rna(xv.x); xv.y = f2tf32_rna(xv.y);
        xv.z = f2tf32_rna(xv.z); xv.w = f2tf32_rna(xv.w);
        *(float4*)(sH + (idx >> 3) * OP_LDH + (idx & 7) * 4) = xv;
        float4 bv = br[i];
        bv.x = f2tf32_rna(bv.x); bv.y = f2tf32_rna(bv.y);
        bv.z = f2tf32_rna(bv.z); bv.w = f2tf32_rna(bv.w);
        *(float4*)(sW + ((tid >> 5) + i * 8) * OP_LDW + c4b * 4) = bv;
    }
    __syncthreads();

    for (int c = 0; c < DIN / 32; ++c) {
        // prefetch next chunk into registers (overlaps with MMAs below)
        if (c < DIN / 32 - 1) {
            const int k0n = (c + 1) * 32;
#pragma unroll
            for (int i = 0; i < 4; ++i) {
                int idx = tid + i * 256;
                ar[i] = *(const float4*)(At + (size_t)(idx >> 3) * DIN + k0n + (idx & 7) * 4);
                br[i] = *(const float4*)(Bt + (size_t)(k0n + (tid >> 5) + i * 8) * DIN + c4b * 4);
            }
        }

        // 64 MMAs per warp on current smem chunk
#pragma unroll
        for (int kc = 0; kc < 4; ++kc) {
            uint32_t af[2][4];
#pragma unroll
            for (int mi = 0; mi < 2; ++mi) {
                const float* r0 = sH + (wm * 32 + mi * 16 + g) * OP_LDH + kc * 8;
                const float* r1 = sH + (wm * 32 + mi * 16 + g + 8) * OP_LDH + kc * 8;
                af[mi][0] = __float_as_uint(r0[t]);
                af[mi][1] = __float_as_uint(r1[t]);
                af[mi][2] = __float_as_uint(r0[t + 4]);
                af[mi][3] = __float_as_uint(r1[t + 4]);
            }
#pragma unroll
            for (int nf = 0; nf < 8; ++nf) {
                uint32_t bfr[2];
                bfr[0] = __float_as_uint(sW[(kc * 8 + t) * OP_LDW + wn * 64 + nf * 8 + g]);
                bfr[1] = __float_as_uint(sW[(kc * 8 + t + 4) * OP_LDW + wn * 64 + nf * 8 + g]);
                mma_tf32(acc[0][nf], af[0], bfr);
                mma_tf32(acc[1][nf], af[1], bfr);
            }
        }
        __syncthreads();

        if (c < DIN / 32 - 1) {
#pragma unroll
            for (int i = 0; i < 4; ++i) {
                int idx = tid + i * 256;
                float4 xv = ar[i];
                xv.x = f2tf32_rna(xv.x); xv.y = f2tf32_rna(xv.y);
                xv.z = f2tf32_rna(xv.z); xv.w = f2tf32_rna(xv.w);
                *(float4*)(sH + (idx >> 3) * OP_LDH + (idx & 7) * 4) = xv;
                float4 bv = br[i];
                bv.x = f2tf32_rna(bv.x); bv.y = f2tf32_rna(bv.y);
                bv.z = f2tf32_rna(bv.z); bv.w = f2tf32_rna(bv.w);
                *(float4*)(sW + ((tid >> 5) + i * 8) * OP_LDW + c4b * 4) = bv;
            }
            __syncthreads();
        }
    }

    // epilogue: c0(g,2t) c1(g,2t+1) c2(g+8,2t) c3(g+8,2t+1)
#pragma unroll
    for (int mi = 0; mi < 2; ++mi) {
        float* r0 = C + (size_t)(m0 + wm * 32 + mi * 16 + g) * DIN + n0 + wn * 64;
        float* r1 = C + (size_t)(m0 + wm * 32 + mi * 16 + g + 8) * DIN + n0 + wn * 64;
#pragma unroll
        for (int nf = 0; nf < 8; ++nf) {
            *(float2*)(r0 + nf * 8 + 2 * t) = make_float2(acc[mi][nf][0], acc[mi][nf][1]);
            *(float2*)(r1 + nf * 8 + 2 * t) = make_float2(acc[mi][nf][2], acc[mi][nf][3]);
        }
    }
}

// ============================================================
// FA2-style flash attention, raw mma.sync tf32 (R6/R7 measured good).
// Change vs R7: Q pre-scaled by NORM*log2e, exp2f instead of __expf
// (identical math, one less FMUL per exp).
// ============================================================
#define LDK 68
#define LDV 72
#define LDP 68
#define ATTN_SMEM ((64 * LDK + 64 * LDV + 128 * LDP) * 4)

__global__ __launch_bounds__(256, 2)
void attn_mma()
{
    extern __shared__ float sm[];
    float* sK = sm;
    float* sV = sK + 64 * LDK;
    float* sP = sV + 64 * LDV;

    const int tid  = threadIdx.x;
    const int w    = tid >> 5;
    const int lane = tid & 31;
    const int g    = lane >> 2;
    const int t    = lane & 3;
    const int q0   = blockIdx.x * 128;
    const int b    = blockIdx.y;
    const int h    = blockIdx.z;

    const float* Qg = g_Q + ((size_t)(h * BATCH + b) * NQ + q0) * HDIM;
    const float* Kg = g_K + (size_t)(h * BATCH + b) * NK * HDIM;
    const float* Vg = g_V + (size_t)(h * BATCH + b) * NK * HDIM;

    const float qscale = NORM_F * LOG2E;
    uint32_t qf[8][4];
#pragma unroll
    for (int kc = 0; kc < 8; ++kc) {
        const float* r0 = Qg + (size_t)(w * 16 + g) * HDIM + kc * 8;
        const float* r1 = Qg + (size_t)(w * 16 + g + 8) * HDIM + kc * 8;
        qf[kc][0] = __float_as_uint(f2tf32_rna(r0[t] * qscale));
        qf[kc][1] = __float_as_uint(f2tf32_rna(r1[t] * qscale));
        qf[kc][2] = __float_as_uint(f2tf32_rna(r0[t + 4] * qscale));
        qf[kc][3] = __float_as_uint(f2tf32_rna(r1[t + 4] * qscale));
    }

    float oacc[8][4];
#pragma unroll
    for (int nt = 0; nt < 8; ++nt)
#pragma unroll
        for (int j = 0; j < 4; ++j) oacc[nt][j] = 0.f;
    float m0 = -1e30f, m1 = -1e30f;
    float l0 = 0.f, l1 = 0.f;

    const unsigned long long* mb_row0 = g_Mb + ((size_t)b * NQ + q0 + w * 16 + g) * (NK / 64);
    const unsigned long long* mb_row1 = mb_row0 + 8 * (NK / 64);
    float* sPw = sP + (w * 16) * LDP;

    for (int kt = 0; kt < NK / 64; ++kt) {
        __syncthreads();
#pragma unroll
        for (int i = 0; i < 4; ++i) {
            int idx = tid + i * 256;
            int r  = idx >> 4;
            int c4 = idx & 15;
            float4 kv = *(const float4*)(Kg + (size_t)(kt * 64 + r) * HDIM + c4 * 4);
            kv.x = f2tf32_rna(kv.x); kv.y = f2tf32_rna(kv.y);
            kv.z = f2tf32_rna(kv.z); kv.w = f2tf32_rna(kv.w);
            *(float4*)(sK + r * LDK + c4 * 4) = kv;
            float4 vv = *(const float4*)(Vg + (size_t)(kt * 64 + r) * HDIM + c4 * 4);
            vv.x = f2tf32_rna(vv.x); vv.y = f2tf32_rna(vv.y);
            vv.z = f2tf32_rna(vv.z); vv.w = f2tf32_rna(vv.w);
            *(float4*)(sV + r * LDV + c4 * 4) = vv;
        }
        __syncthreads();

        float sacc[8][4];
#pragma unroll
        for (int nt = 0; nt < 8; ++nt) {
#pragma unroll
            for (int j = 0; j < 4; ++j) sacc[nt][j] = 0.f;
#pragma unroll
            for (int kc = 0; kc < 8; ++kc) {
                uint32_t bfr[2];
                const float* kb = sK + (nt * 8 + g) * LDK + kc * 8;
                bfr[0] = __float_as_uint(kb[t]);
                bfr[1] = __float_as_uint(kb[t + 4]);
                mma_tf32(sacc[nt], qf[kc], bfr);
            }
        }

        unsigned long long mb0 = mb_row0[kt];
        unsigned long long mb1 = mb_row1[kt];
        float tmax0 = -1e30f, tmax1 = -1e30f;
#pragma unroll
        for (int nt = 0; nt < 8; ++nt) {
            int c0 = nt * 8 + 2 * t, c1 = c0 + 1;
            if ((mb0 >> c0) & 1ull) sacc[nt][0] = -1e30f;
            if ((mb0 >> c1) & 1ull) sacc[nt][1] = -1e30f;
            if ((mb1 >> c0) & 1ull) sacc[nt][2] = -1e30f;
            if ((mb1 >> c1) & 1ull) sacc[nt][3] = -1e30f;
            tmax0 = fmaxf(tmax0, fmaxf(sacc[nt][0], sacc[nt][1]));
            tmax1 = fmaxf(tmax1, fmaxf(sacc[nt][2], sacc[nt][3]));
        }
        tmax0 = fmaxf(tmax0, __shfl_xor_sync(0xffffffffu, tmax0, 1));
        tmax0 = fmaxf(tmax0, __shfl_xor_sync(0xffffffffu, tmax0, 2));
        tmax1 = fmaxf(tmax1, __shfl_xor_sync(0xffffffffu, tmax1, 1));
        tmax1 = fmaxf(tmax1, __shfl_xor_sync(0xffffffffu, tmax1, 2));

        float mn0 = fmaxf(m0, tmax0);
        float mn1 = fmaxf(m1, tmax1);
        float sc0 = exp2f(m0 - mn0);
        float sc1 = exp2f(m1 - mn1);
        m0 = mn0; m1 = mn1;

        float ps0 = 0.f, ps1 = 0.f;
#pragma unroll
        for (int nt = 0; nt < 8; ++nt) {
            float p0 = exp2f(sacc[nt][0] - mn0);
            float p1 = exp2f(sacc[nt][1] - mn0);
            float p2 = exp2f(sacc[nt][2] - mn1);
            float p3 = exp2f(sacc[nt][3] - mn1);
            ps0 += p0 + p1;
            ps1 += p2 + p3;
            float2 lo = make_float2(f2tf32_rna(p0), f2tf32_rna(p1));
            float2 hi = make_float2(f2tf32_rna(p2), f2tf32_rna(p3));
            *(float2*)(sPw + g * LDP + nt * 8 + 2 * t) = lo;
            *(float2*)(sPw + (g + 8) * LDP + nt * 8 + 2 * t) = hi;
        }
        ps0 += __shfl_xor_sync(0xffffffffu, ps0, 1);
        ps0 += __shfl_xor_sync(0xffffffffu, ps0, 2);
        ps1 += __shfl_xor_sync(0xffffffffu, ps1, 1);
        ps1 += __shfl_xor_sync(0xffffffffu, ps1, 2);
        l0 = l0 * sc0 + ps0;
        l1 = l1 * sc1 + ps1;

#pragma unroll
        for (int nt = 0; nt < 8; ++nt) {
            oacc[nt][0] *= sc0; oacc[nt][1] *= sc0;
            oacc[nt][2] *= sc1; oacc[nt][3] *= sc1;
        }
        __syncwarp();

#pragma unroll
        for (int kc = 0; kc < 8; ++kc) {
            uint32_t pa[4];
            const float* p0r = sPw + g * LDP + kc * 8;
            const float* p1r = sPw + (g + 8) * LDP + kc * 8;
            pa[0] = __float_as_uint(p0r[t]);
            pa[1] = __float_as_uint(p1r[t]);
            pa[2] = __float_as_uint(p0r[t + 4]);
            pa[3] = __float_as_uint(p1r[t + 4]);
#pragma unroll
            for (int nt = 0; nt < 8; ++nt) {
                uint32_t bfr[2];
                bfr[0] = __float_as_uint(sV[(kc * 8 + t) * LDV + nt * 8 + g]);
                bfr[1] = __float_as_uint(sV[(kc * 8 + t + 4) * LDV + nt * 8 + g]);
                mma_tf32(oacc[nt], pa, bfr);
            }
        }
        __syncwarp();
    }

    float inv0 = (l0 > 0.f) ? (1.f / l0) : 0.f;
    float inv1 = (l1 > 0.f) ? (1.f / l1) : 0.f;
    float* o0 = g_H + ((size_t)(b * NQ + q0 + w * 16 + g)) * DIN + h * HDIM;
    float* o1 = g_H + ((size_t)(b * NQ + q0 + w * 16 + g + 8)) * DIN + h * HDIM;
#pragma unroll
    for (int nt = 0; nt < 8; ++nt) {
        *(float2*)(o0 + nt * 8 + 2 * t) = make_float2(oacc[nt][0] * inv0, oacc[nt][1] * inv0);
        *(float2*)(o1 + nt * 8 + 2 * t) = make_float2(oacc[nt][2] * inv1, oacc[nt][3] * inv1);
    }
}

// ============================================================
extern "C" void kernel_launch(void* const* d_in, const int* in_sizes, int n_in,
                              void* d_out, int out_size)
{
    const float* q  = (const float*)d_in[0];
    const float* k  = (const float*)d_in[1];
    const float* v  = (const float*)d_in[2];
    const int*   mask = (const int*)d_in[3];
    const float* Wq = (const float*)d_in[4];
    const float* Wk = (const float*)d_in[5];
    const float* Wv = (const float*)d_in[6];
    const float* Wo = (const float*)d_in[7];
    float* out = (float*)d_out;

    float *pH;
    cudaGetSymbolAddress((void**)&pH, g_H);

    static bool attr_set = false;
    if (!attr_set) {
        cudaFuncSetAttribute(attn_mma,
                             cudaFuncAttributeMaxDynamicSharedMemorySize,
                             ATTN_SMEM);
        attr_set = true;
    }

    // QKV projections: exact fp32 SIMT (R7 config)
    qkv_proj2<<<dim3(BN_TOT / QBM, DIN / QBN, 3), 256>>>(q, k, v, Wq, Wk, Wv);

    // Pack mask to bitmasks
    pack_mask<<<(BN_TOT * (NK / 64)) / 8, 256>>>(mask);

    // Flash attention (raw mma.sync tf32, register softmax, exp2)
    attn_mma<<<dim3(NQ / 128, BATCH, NHEADS), 256, ATTN_SMEM>>>();

    // Output projection: raw mma.sync tf32
    out_proj3<<<dim3(BN_TOT / 128, DIN / 128), 256>>>(pH, Wo, out);
}

// round 10
// speedup vs baseline: 1.5496x; 1.5496x over previous
#include <cuda_runtime.h>
#include <cuda_bf16.h>
#include <cstdint>

// Problem constants
#define BATCH   16
#define NQ      1024
#define NK      1024
#define DIN     512
#define NHEADS  8
#define HDIM    64
#define BN_TOT  (BATCH * NQ)       // 16384
#define NORM_F  0.125f             // 1/sqrt(64)
#define LOG2E   1.4426950408889634f

// -------- scratch (device globals: allocation-free) --------
__device__ float g_Q[(size_t)NHEADS * BN_TOT * HDIM];   // [h][bn][64]
__device__ float g_K[(size_t)NHEADS * BN_TOT * HDIM];
__device__ float g_V[(size_t)NHEADS * BN_TOT * HDIM];
__device__ float g_H[(size_t)BN_TOT * DIN];             // [bn][h*64+v]
__device__ unsigned long long g_Mb[(size_t)BN_TOT * (NK / 64)];  // packed mask bits

__device__ __forceinline__ float f2tf32_rna(float x) {
    uint32_t r;
    asm("cvt.rna.tf32.f32 %0, %1;" : "=r"(r) : "f"(x));
    return __uint_as_float(r);
}

// Hardware EX2 (single MUFU op, no library fallback)
__device__ __forceinline__ float ex2_approx(float x) {
    float r;
    asm("ex2.approx.f32 %0, %1;" : "=f"(r) : "f"(x));
    return r;
}

// m16n8k8 tf32 mma (g=lane>>2, t=lane&3):
//   A: a0(g,t) a1(g+8,t) a2(g,t+4) a3(g+8,t+4)
//   B: b0(k=t,n=g) b1(k=t+4,n=g)
//   C: c0(g,2t) c1(g,2t+1) c2(g+8,2t) c3(g+8,2t+1)
__device__ __forceinline__ void mma_tf32(float* c, const uint32_t* a, const uint32_t* b) {
    asm volatile(
        "mma.sync.aligned.m16n8k8.row.col.f32.tf32.tf32.f32 "
        "{%0,%1,%2,%3}, {%4,%5,%6,%7}, {%8,%9}, {%0,%1,%2,%3};"
        : "+f"(c[0]), "+f"(c[1]), "+f"(c[2]), "+f"(c[3])
        : "r"(a[0]), "r"(a[1]), "r"(a[2]), "r"(a[3]), "r"(b[0]), "r"(b[1]));
}

// ============================================================
// Fused QKV projection, exact fp32 SIMT (R7 version — measured best).
// 128x128 tile, 256 threads, 8x8 microtile, BK=16, smem double-buffered.
// grid = (128 m-tiles, 4 n-tiles, 3 ops)
// ============================================================
#define QBM 128
#define QBN 128
#define QBK 16

__global__ __launch_bounds__(256)
void qkv_proj2(const float* __restrict__ q,
               const float* __restrict__ k,
               const float* __restrict__ v,
               const float* __restrict__ Wq,
               const float* __restrict__ Wk,
               const float* __restrict__ Wv)
{
    __shared__ float Xs[2][QBK][QBM];
    __shared__ float Ws[2][QBK][QBN];

    const int tid = threadIdx.x;
    const int tx  = tid & 15;
    const int ty  = tid >> 4;
    const int op  = blockIdx.z;
    const int m0  = blockIdx.x * QBM;
    const int n0  = blockIdx.y * QBN;

    const float* X = (op == 0 ? q : (op == 1 ? k : v));
    const float* W = (op == 0 ? Wq : (op == 1 ? Wk : Wv));
    float* Cb      = (op == 0 ? g_Q : (op == 1 ? g_K : g_V));

    const int mA  = tid & 127;
    const int k4a = tid >> 7;
    const float* Ag = X + (size_t)(m0 + mA) * DIN;
    const int kkB = tid >> 5;
    const int c4  = tid & 31;
    const float* Bg = W + (size_t)((n0 + c4 * 4) >> 6) * (DIN * HDIM)
                        + ((n0 + c4 * 4) & 63);

    float acc[8][8];
#pragma unroll
    for (int i = 0; i < 8; i++)
#pragma unroll
        for (int j = 0; j < 8; j++) acc[i][j] = 0.f;

    float4 ar[2], br[2];
#pragma unroll
    for (int i = 0; i < 2; ++i) {
        ar[i] = *(const float4*)(Ag + (k4a + 2 * i) * 4);
        br[i] = *(const float4*)(Bg + (size_t)(kkB + 8 * i) * HDIM);
    }
#pragma unroll
    for (int i = 0; i < 2; ++i) {
        int kr = (k4a + 2 * i) * 4;
        Xs[0][kr + 0][mA] = ar[i].x;
        Xs[0][kr + 1][mA] = ar[i].y;
        Xs[0][kr + 2][mA] = ar[i].z;
        Xs[0][kr + 3][mA] = ar[i].w;
        *(float4*)(&Ws[0][kkB + 8 * i][c4 * 4]) = br[i];
    }
    __syncthreads();

    for (int c = 0; c < DIN / QBK; ++c) {
        const int cur = c & 1;
        if (c < DIN / QBK - 1) {
            const int k0n = (c + 1) * QBK;
#pragma unroll
            for (int i = 0; i < 2; ++i) {
                ar[i] = *(const float4*)(Ag + k0n + (k4a + 2 * i) * 4);
                br[i] = *(const float4*)(Bg + (size_t)(k0n + kkB + 8 * i) * HDIM);
            }
        }

#pragma unroll
        for (int kk = 0; kk < QBK; ++kk) {
            float a[8], b[8];
            *(float4*)(a)     = *(const float4*)(&Xs[cur][kk][ty * 8]);
            *(float4*)(a + 4) = *(const float4*)(&Xs[cur][kk][ty * 8 + 4]);
            *(float4*)(b)     = *(const float4*)(&Ws[cur][kk][tx * 8]);
            *(float4*)(b + 4) = *(const float4*)(&Ws[cur][kk][tx * 8 + 4]);
#pragma unroll
            for (int i = 0; i < 8; i++)
#pragma unroll
                for (int j = 0; j < 8; j++)
                    acc[i][j] = fmaf(a[i], b[j], acc[i][j]);
        }

        if (c < DIN / QBK - 1) {
            const int nxt = cur ^ 1;
#pragma unroll
            for (int i = 0; i < 2; ++i) {
                int kr = (k4a + 2 * i) * 4;
                Xs[nxt][kr + 0][mA] = ar[i].x;
                Xs[nxt][kr + 1][mA] = ar[i].y;
                Xs[nxt][kr + 2][mA] = ar[i].z;
                Xs[nxt][kr + 3][mA] = ar[i].w;
                *(float4*)(&Ws[nxt][kkB + 8 * i][c4 * 4]) = br[i];
            }
            __syncthreads();
        }
    }

    const int cgl = n0 + tx * 8;
    const int h   = cgl >> 6;
    const int nh  = cgl & 63;
    float* Crow = Cb + (size_t)h * BN_TOT * HDIM
                     + (size_t)(m0 + ty * 8) * HDIM + nh;
#pragma unroll
    for (int i = 0; i < 8; i++) {
        *(float4*)(Crow + (size_t)i * HDIM)     =
            make_float4(acc[i][0], acc[i][1], acc[i][2], acc[i][3]);
        *(float4*)(Crow + (size_t)i * HDIM + 4) =
            make_float4(acc[i][4], acc[i][5], acc[i][6], acc[i][7]);
    }
}

// ============================================================
// Mask pack: 64 int32 -> 1 uint64 bitmask per (bq, key-tile) via ballot.
// ============================================================
__global__ __launch_bounds__(256)
void pack_mask(const int* __restrict__ mask)
{
    int w = (blockIdx.x * 256 + threadIdx.x) >> 5;
    int lane = threadIdx.x & 31;
    const int* src = mask + (size_t)w * 64;
    unsigned lo = __ballot_sync(0xffffffffu, src[lane] != 0);
    unsigned hi = __ballot_sync(0xffffffffu, src[lane + 32] != 0);
    if (lane == 0)
        g_Mb[w] = ((unsigned long long)hi << 32) | (unsigned long long)lo;
}

// ============================================================
// Out projection with RAW mma.sync (R9 version — measured good, 114us).
// C[16384,512] = H[16384,512] @ Wo[512,512] (Wo row-major [k][e]).
// grid = (128 m-tiles, 4 n-tiles)
// ============================================================
#define OP_LDH 40    // 32 + 8
#define OP_LDW 136   // 128 + 8

__global__ __launch_bounds__(256, 2)
void out_proj3(const float* __restrict__ A,
               const float* __restrict__ B,
               float* __restrict__ C)
{
    __shared__ float sH[128 * OP_LDH];   // 20.0 KB
    __shared__ float sW[32 * OP_LDW];    // 17.4 KB

    const int tid  = threadIdx.x;
    const int w    = tid >> 5;
    const int lane = tid & 31;
    const int g    = lane >> 2;
    const int t    = lane & 3;
    const int wm   = w & 3;
    const int wn   = w >> 2;
    const int m0   = blockIdx.x * 128;
    const int n0   = blockIdx.y * 128;

    const float* At = A + (size_t)m0 * DIN;
    const float* Bt = B + n0;

    const int c4b = tid & 31;

    float acc[2][8][4];
#pragma unroll
    for (int mi = 0; mi < 2; ++mi)
#pragma unroll
        for (int nf = 0; nf < 8; ++nf)
#pragma unroll
            for (int j = 0; j < 4; ++j) acc[mi][nf][j] = 0.f;

    float4 ar[4], br[4];
#pragma unroll
    for (int i = 0; i < 4; ++i) {
        int idx = tid + i * 256;
        ar[i] = *(const float4*)(At + (size_t)(idx >> 3) * DIN + (idx & 7) * 4);
        br[i] = *(const float4*)(Bt + (size_t)((tid >> 5) + i * 8) * DIN + c4b * 4);
    }
#pragma unroll
    for (int i = 0; i < 4; ++i) {
        int idx = tid + i * 256;
        float4 xv = ar[i];
        xv.x = f2tf32_rna(xv.x); xv.y = f2tf32_rna(xv.y);
        xv.z = f2tf32_rna(xv.z); xv.w = f2tf32_rna(xv.w);
        *(float4*)(sH + (idx >> 3) * OP_LDH + (idx & 7) * 4) = xv;
        float4 bv = br[i];
        bv.x = f2tf32_rna(bv.x); bv.y = f2tf32_rna(bv.y);
        bv.z = f2tf32_rna(bv.z); bv.w = f2tf32_rna(bv.w);
        *(float4*)(sW + ((tid >> 5) + i * 8) * OP_LDW + c4b * 4) = bv;
    }
    __syncthreads();

    for (int c = 0; c < DIN / 32; ++c) {
        if (c < DIN / 32 - 1) {
            const int k0n = (c + 1) * 32;
#pragma unroll
            for (int i = 0; i < 4; ++i) {
                int idx = tid + i * 256;
                ar[i] = *(const float4*)(At + (size_t)(idx >> 3) * DIN + k0n + (idx & 7) * 4);
                br[i] = *(const float4*)(Bt + (size_t)(k0n + (tid >> 5) + i * 8) * DIN + c4b * 4);
            }
        }

#pragma unroll
        for (int kc = 0; kc < 4; ++kc) {
            uint32_t af[2][4];
#pragma unroll
            for (int mi = 0; mi < 2; ++mi) {
                const float* r0 = sH + (wm * 32 + mi * 16 + g) * OP_LDH + kc * 8;
                const float* r1 = sH + (wm * 32 + mi * 16 + g + 8) * OP_LDH + kc * 8;
                af[mi][0] = __float_as_uint(r0[t]);
                af[mi][1] = __float_as_uint(r1[t]);
                af[mi][2] = __float_as_uint(r0[t + 4]);
                af[mi][3] = __float_as_uint(r1[t + 4]);
            }
#pragma unroll
            for (int nf = 0; nf < 8; ++nf) {
                uint32_t bfr[2];
                bfr[0] = __float_as_uint(sW[(kc * 8 + t) * OP_LDW + wn * 64 + nf * 8 + g]);
                bfr[1] = __float_as_uint(sW[(kc * 8 + t + 4) * OP_LDW + wn * 64 + nf * 8 + g]);
                mma_tf32(acc[0][nf], af[0], bfr);
                mma_tf32(acc[1][nf], af[1], bfr);
            }
        }
        __syncthreads();

        if (c < DIN / 32 - 1) {
#pragma unroll
            for (int i = 0; i < 4; ++i) {
                int idx = tid + i * 256;
                float4 xv = ar[i];
                xv.x = f2tf32_rna(xv.x); xv.y = f2tf32_rna(xv.y);
                xv.z = f2tf32_rna(xv.z); xv.w = f2tf32_rna(xv.w);
                *(float4*)(sH + (idx >> 3) * OP_LDH + (idx & 7) * 4) = xv;
                float4 bv = br[i];
                bv.x = f2tf32_rna(bv.x); bv.y = f2tf32_rna(bv.y);
                bv.z = f2tf32_rna(bv.z); bv.w = f2tf32_rna(bv.w);
                *(float4*)(sW + ((tid >> 5) + i * 8) * OP_LDW + c4b * 4) = bv;
            }
            __syncthreads();
        }
    }

#pragma unroll
    for (int mi = 0; mi < 2; ++mi) {
        float* r0 = C + (size_t)(m0 + wm * 32 + mi * 16 + g) * DIN + n0 + wn * 64;
        float* r1 = C + (size_t)(m0 + wm * 32 + mi * 16 + g + 8) * DIN + n0 + wn * 64;
#pragma unroll
        for (int nf = 0; nf < 8; ++nf) {
            *(float2*)(r0 + nf * 8 + 2 * t) = make_float2(acc[mi][nf][0], acc[mi][nf][1]);
            *(float2*)(r1 + nf * 8 + 2 * t) = make_float2(acc[mi][nf][2], acc[mi][nf][3]);
        }
    }
}

// ============================================================
// FA2-style flash attention, raw mma.sync tf32.
// R10 fix: exponentials via explicit ex2.approx.f32 (hardware MUFU EX2),
// Q pre-scaled by NORM*log2e. (R9's exp2f hit the slow libm path.)
// ============================================================
#define LDK 68
#define LDV 72
#define LDP 68
#define ATTN_SMEM ((64 * LDK + 64 * LDV + 128 * LDP) * 4)

__global__ __launch_bounds__(256, 2)
void attn_mma()
{
    extern __shared__ float sm[];
    float* sK = sm;
    float* sV = sK + 64 * LDK;
    float* sP = sV + 64 * LDV;

    const int tid  = threadIdx.x;
    const int w    = tid >> 5;
    const int lane = tid & 31;
    const int g    = lane >> 2;
    const int t    = lane & 3;
    const int q0   = blockIdx.x * 128;
    const int b    = blockIdx.y;
    const int h    = blockIdx.z;

    const float* Qg = g_Q + ((size_t)(h * BATCH + b) * NQ + q0) * HDIM;
    const float* Kg = g_K + (size_t)(h * BATCH + b) * NK * HDIM;
    const float* Vg = g_V + (size_t)(h * BATCH + b) * NK * HDIM;

    const float qscale = NORM_F * LOG2E;
    uint32_t qf[8][4];
#pragma unroll
    for (int kc = 0; kc < 8; ++kc) {
        const float* r0 = Qg + (size_t)(w * 16 + g) * HDIM + kc * 8;
        const float* r1 = Qg + (size_t)(w * 16 + g + 8) * HDIM + kc * 8;
        qf[kc][0] = __float_as_uint(f2tf32_rna(r0[t] * qscale));
        qf[kc][1] = __float_as_uint(f2tf32_rna(r1[t] * qscale));
        qf[kc][2] = __float_as_uint(f2tf32_rna(r0[t + 4] * qscale));
        qf[kc][3] = __float_as_uint(f2tf32_rna(r1[t + 4] * qscale));
    }

    float oacc[8][4];
#pragma unroll
    for (int nt = 0; nt < 8; ++nt)
#pragma unroll
        for (int j = 0; j < 4; ++j) oacc[nt][j] = 0.f;
    float m0 = -1e30f, m1 = -1e30f;
    float l0 = 0.f, l1 = 0.f;

    const unsigned long long* mb_row0 = g_Mb + ((size_t)b * NQ + q0 + w * 16 + g) * (NK / 64);
    const unsigned long long* mb_row1 = mb_row0 + 8 * (NK / 64);
    float* sPw = sP + (w * 16) * LDP;

    for (int kt = 0; kt < NK / 64; ++kt) {
        __syncthreads();
#pragma unroll
        for (int i = 0; i < 4; ++i) {
            int idx = tid + i * 256;
            int r  = idx >> 4;
            int c4 = idx & 15;
            float4 kv = *(const float4*)(Kg + (size_t)(kt * 64 + r) * HDIM + c4 * 4);
            kv.x = f2tf32_rna(kv.x); kv.y = f2tf32_rna(kv.y);
            kv.z = f2tf32_rna(kv.z); kv.w = f2tf32_rna(kv.w);
            *(float4*)(sK + r * LDK + c4 * 4) = kv;
            float4 vv = *(const float4*)(Vg + (size_t)(kt * 64 + r) * HDIM + c4 * 4);
            vv.x = f2tf32_rna(vv.x); vv.y = f2tf32_rna(vv.y);
            vv.z = f2tf32_rna(vv.z); vv.w = f2tf32_rna(vv.w);
            *(float4*)(sV + r * LDV + c4 * 4) = vv;
        }
        __syncthreads();

        float sacc[8][4];
#pragma unroll
        for (int nt = 0; nt < 8; ++nt) {
#pragma unroll
            for (int j = 0; j < 4; ++j) sacc[nt][j] = 0.f;
#pragma unroll
            for (int kc = 0; kc < 8; ++kc) {
                uint32_t bfr[2];
                const float* kb = sK + (nt * 8 + g) * LDK + kc * 8;
                bfr[0] = __float_as_uint(kb[t]);
                bfr[1] = __float_as_uint(kb[t + 4]);
                mma_tf32(sacc[nt], qf[kc], bfr);
            }
        }

        unsigned long long mb0 = mb_row0[kt];
        unsigned long long mb1 = mb_row1[kt];
        float tmax0 = -1e30f, tmax1 = -1e30f;
#pragma unroll
        for (int nt = 0; nt < 8; ++nt) {
            int c0 = nt * 8 + 2 * t, c1 = c0 + 1;
            if ((mb0 >> c0) & 1ull) sacc[nt][0] = -1e30f;
            if ((mb0 >> c1) & 1ull) sacc[nt][1] = -1e30f;
            if ((mb1 >> c0) & 1ull) sacc[nt][2] = -1e30f;
            if ((mb1 >> c1) & 1ull) sacc[nt][3] = -1e30f;
            tmax0 = fmaxf(tmax0, fmaxf(sacc[nt][0], sacc[nt][1]));
            tmax1 = fmaxf(tmax1, fmaxf(sacc[nt][2], sacc[nt][3]));
        }
        tmax0 = fmaxf(tmax0, __shfl_xor_sync(0xffffffffu, tmax0, 1));
        tmax0 = fmaxf(tmax0, __shfl_xor_sync(0xffffffffu, tmax0, 2));
        tmax1 = fmaxf(tmax1, __shfl_xor_sync(0xffffffffu, tmax1, 1));
        tmax1 = fmaxf(tmax1, __shfl_xor_sync(0xffffffffu, tmax1, 2));

        float mn0 = fmaxf(m0, tmax0);
        float mn1 = fmaxf(m1, tmax1);
        float sc0 = ex2_approx(m0 - mn0);
        float sc1 = ex2_approx(m1 - mn1);
        m0 = mn0; m1 = mn1;

        float ps0 = 0.f, ps1 = 0.f;
#pragma unroll
        for (int nt = 0; nt < 8; ++nt) {
            float p0 = ex2_approx(sacc[nt][0] - mn0);
            float p1 = ex2_approx(sacc[nt][1] - mn0);
            float p2 = ex2_approx(sacc[nt][2] - mn1);
            float p3 = ex2_approx(sacc[nt][3] - mn1);
            ps0 += p0 + p1;
            ps1 += p2 + p3;
            float2 lo = make_float2(f2tf32_rna(p0), f2tf32_rna(p1));
            float2 hi = make_float2(f2tf32_rna(p2), f2tf32_rna(p3));
            *(float2*)(sPw + g * LDP + nt * 8 + 2 * t) = lo;
            *(float2*)(sPw + (g + 8) * LDP + nt * 8 + 2 * t) = hi;
        }
        ps0 += __shfl_xor_sync(0xffffffffu, ps0, 1);
        ps0 += __shfl_xor_sync(0xffffffffu, ps0, 2);
        ps1 += __shfl_xor_sync(0xffffffffu, ps1, 1);
        ps1 += __shfl_xor_sync(0xffffffffu, ps1, 2);
        l0 = l0 * sc0 + ps0;
        l1 = l1 * sc1 + ps1;

#pragma unroll
        for (int nt = 0; nt < 8; ++nt) {
            oacc[nt][0] *= sc0; oacc[nt][1] *= sc0;
            oacc[nt][2] *= sc1; oacc[nt][3] *= sc1;
        }
        __syncwarp();

#pragma unroll
        for (int kc = 0; kc < 8; ++kc) {
            uint32_t pa[4];
            const float* p0r = sPw + g * LDP + kc * 8;
            const float* p1r = sPw + (g + 8) * LDP + kc * 8;
            pa[0] = __float_as_uint(p0r[t]);
            pa[1] = __float_as_uint(p1r[t]);
            pa[2] = __float_as_uint(p0r[t + 4]);
            pa[3] = __float_as_uint(p1r[t + 4]);
#pragma unroll
            for (int nt = 0; nt < 8; ++nt) {
                uint32_t bfr[2];
                bfr[0] = __float_as_uint(sV[(kc * 8 + t) * LDV + nt * 8 + g]);
                bfr[1] = __float_as_uint(sV[(kc * 8 + t + 4) * LDV + nt * 8 + g]);
                mma_tf32(oacc[nt], pa, bfr);
            }
        }
        __syncwarp();
    }

    float inv0 = (l0 > 0.f) ? (1.f / l0) : 0.f;
    float inv1 = (l1 > 0.f) ? (1.f / l1) : 0.f;
    float* o0 = g_H + ((size_t)(b * NQ + q0 + w * 16 + g)) * DIN + h * HDIM;
    float* o1 = g_H + ((size_t)(b * NQ + q0 + w * 16 + g + 8)) * DIN + h * HDIM;
#pragma unroll
    for (int nt = 0; nt < 8; ++nt) {
        *(float2*)(o0 + nt * 8 + 2 * t) = make_float2(oacc[nt][0] * inv0, oacc[nt][1] * inv0);
        *(float2*)(o1 + nt * 8 + 2 * t) = make_float2(oacc[nt][2] * inv1, oacc[nt][3] * inv1);
    }
}

// ============================================================
extern "C" void kernel_launch(void* const* d_in, const int* in_sizes, int n_in,
                              void* d_out, int out_size)
{
    const float* q  = (const float*)d_in[0];
    const float* k  = (const float*)d_in[1];
    const float* v  = (const float*)d_in[2];
    const int*   mask = (const int*)d_in[3];
    const float* Wq = (const float*)d_in[4];
    const float* Wk = (const float*)d_in[5];
    const float* Wv = (const float*)d_in[6];
    const float* Wo = (const float*)d_in[7];
    float* out = (float*)d_out;

    float *pH;
    cudaGetSymbolAddress((void**)&pH, g_H);

    static bool attr_set = false;
    if (!attr_set) {
        cudaFuncSetAttribute(attn_mma,
                             cudaFuncAttributeMaxDynamicSharedMemorySize,
                             ATTN_SMEM);
        attr_set = true;
    }

    // QKV projections: exact fp32 SIMT (R7 config)
    qkv_proj2<<<dim3(BN_TOT / QBM, DIN / QBN, 3), 256>>>(q, k, v, Wq, Wk, Wv);

    // Pack mask to bitmasks
    pack_mask<<<(BN_TOT * (NK / 64)) / 8, 256>>>(mask);

    // Flash attention (raw mma.sync tf32, register softmax, HW EX2)
    attn_mma<<<dim3(NQ / 128, BATCH, NHEADS), 256, ATTN_SMEM>>>();

    // Output projection: raw mma.sync tf32
    out_proj3<<<dim3(BN_TOT / 128, DIN / 128), 256>>>(pH, Wo, out);
}

// round 12
// speedup vs baseline: 2.2648x; 1.4615x over previous
#include <cuda_runtime.h>
#include <cuda_bf16.h>
#include <cstdint>

// Problem constants
#define BATCH   16
#define NQ      1024
#define NK      1024
#define DIN     512
#define NHEADS  8
#define HDIM    64
#define BN_TOT  (BATCH * NQ)       // 16384
#define NORM_F  0.125f             // 1/sqrt(64)
#define LOG2E   1.4426950408889634f

// -------- scratch (device globals: allocation-free) --------
__device__ float g_Q[(size_t)NHEADS * BN_TOT * HDIM];   // [h][bn][64]
__device__ float g_K[(size_t)NHEADS * BN_TOT * HDIM];
__device__ float g_V[(size_t)NHEADS * BN_TOT * HDIM];
__device__ float g_H[(size_t)BN_TOT * DIN];             // [bn][h*64+v]
__device__ unsigned long long g_Mb[(size_t)BN_TOT * (NK / 64)];  // packed mask bits
// bf16 hi/lo split of QKV weights, layout [op][n_global(512)][k(512)]
__device__ __nv_bfloat16 g_Wbh[(size_t)3 * 512 * 512];
__device__ __nv_bfloat16 g_Wbl[(size_t)3 * 512 * 512];

__device__ __forceinline__ float f2tf32_rna(float x) {
    uint32_t r;
    asm("cvt.rna.tf32.f32 %0, %1;" : "=r"(r) : "f"(x));
    return __uint_as_float(r);
}

// Hardware EX2 (single MUFU op)
__device__ __forceinline__ float ex2_approx(float x) {
    float r;
    asm("ex2.approx.f32 %0, %1;" : "=f"(r) : "f"(x));
    return r;
}

// m16n8k8 tf32 mma (g=lane>>2, t=lane&3):
//   A: a0(g,t) a1(g+8,t) a2(g,t+4) a3(g+8,t+4)
//   B: b0(k=t,n=g) b1(k=t+4,n=g)
//   C: c0(g,2t) c1(g,2t+1) c2(g+8,2t) c3(g+8,2t+1)
__device__ __forceinline__ void mma_tf32(float* c, const uint32_t* a, const uint32_t* b) {
    asm volatile(
        "mma.sync.aligned.m16n8k8.row.col.f32.tf32.tf32.f32 "
        "{%0,%1,%2,%3}, {%4,%5,%6,%7}, {%8,%9}, {%0,%1,%2,%3};"
        : "+f"(c[0]), "+f"(c[1]), "+f"(c[2]), "+f"(c[3])
        : "r"(a[0]), "r"(a[1]), "r"(a[2]), "r"(a[3]), "r"(b[0]), "r"(b[1]));
}

// m16n8k16 bf16 mma. Each 32-bit reg = 2 bf16 along K.
//   A: a0(g, 2t..2t+1) a1(g+8, 2t..) a2(g, 2t+8..) a3(g+8, 2t+8..)
//   B: b0(k=2t..2t+1, n=g) b1(k=2t+8.., n=g)
//   C: c0(g,2t) c1(g,2t+1) c2(g+8,2t) c3(g+8,2t+1)
__device__ __forceinline__ void mma_bf16(float* c, const uint32_t* a,
                                         uint32_t b0, uint32_t b1) {
    asm volatile(
        "mma.sync.aligned.m16n8k16.row.col.f32.bf16.bf16.f32 "
        "{%0,%1,%2,%3}, {%4,%5,%6,%7}, {%8,%9}, {%0,%1,%2,%3};"
        : "+f"(c[0]), "+f"(c[1]), "+f"(c[2]), "+f"(c[3])
        : "r"(a[0]), "r"(a[1]), "r"(a[2]), "r"(a[3]), "r"(b0), "r"(b1));
}

// ============================================================
// W prep: split QKV weights to bf16 hi/lo, transposed to [op][n][k].
// W_src is head-major: [h][k][64]; n_global = h*64 + nh.
// ============================================================
__global__ __launch_bounds__(256)
void w_prep(const float* __restrict__ Wq,
            const float* __restrict__ Wk,
            const float* __restrict__ Wv)
{
    size_t idx = (size_t)blockIdx.x * 256 + threadIdx.x;   // [op][n][k]
    int k  = idx & 511;
    int n  = (idx >> 9) & 511;
    int op = (int)(idx >> 18);
    const float* W = (op == 0 ? Wq : (op == 1 ? Wk : Wv));
    float w = W[(size_t)((n >> 6) * 512 + k) * 64 + (n & 63)];
    __nv_bfloat16 hi = __float2bfloat16_rn(w);
    __nv_bfloat16 lo = __float2bfloat16_rn(w - __bfloat162float(hi));
    g_Wbh[idx] = hi;
    g_Wbl[idx] = lo;
}

// ============================================================
// QKV projection via bf16x3 split tensor-core GEMM (exact to ~2^-16).
// C[16384,512] = X[16384,512] @ W[512,512] per op.
// Block 256 thr / 8 warps (wm: 4x32 M-rows, wn: 2x64 N-cols); per warp
// 32x64 tile, acc[2][8][4] fp32. K-chunks of 32 (2 bf16-mma k-steps).
// 3 MMA terms: hi*hi + hi*lo + lo*hi. Epilogue scatters to head layout.
// grid = (128 m-tiles, 4 n-tiles, 3 ops)
// R12 fix: QLD 36 -> 40. Row stride 80 B: 16B-aligned (uint4 stores legal);
// frag-load words = col*20 + kb/2 + t -> 20g mod 32 = {0,20,8,28,16,4,24,12}
// + t in 0..3 covers all 32 banks once -> conflict-free.
// ============================================================
#define QLD 40

__global__ __launch_bounds__(256, 2)
void qkv_bf(const float* __restrict__ q,
            const float* __restrict__ k,
            const float* __restrict__ v)
{
    __shared__ __nv_bfloat16 sAh[128 * QLD];   // 10.2 KB each
    __shared__ __nv_bfloat16 sAl[128 * QLD];
    __shared__ __nv_bfloat16 sWh[128 * QLD];
    __shared__ __nv_bfloat16 sWl[128 * QLD];

    const int tid  = threadIdx.x;
    const int w    = tid >> 5;
    const int lane = tid & 31;
    const int g    = lane >> 2;
    const int t    = lane & 3;
    const int wm   = w & 3;
    const int wn   = w >> 2;
    const int op   = blockIdx.z;
    const int m0   = blockIdx.x * 128;
    const int n0   = blockIdx.y * 128;

    const float* X = (op == 0 ? q : (op == 1 ? k : v));
    float* Cb      = (op == 0 ? g_Q : (op == 1 ? g_K : g_V));
    const __nv_bfloat16* Wh = g_Wbh + ((size_t)op * 512 + n0) * 512;
    const __nv_bfloat16* Wl = g_Wbl + ((size_t)op * 512 + n0) * 512;

    float acc[2][8][4];
#pragma unroll
    for (int mi = 0; mi < 2; ++mi)
#pragma unroll
        for (int nf = 0; nf < 8; ++nf)
#pragma unroll
            for (int j = 0; j < 4; ++j) acc[mi][nf][j] = 0.f;

    for (int c = 0; c < DIN / 32; ++c) {
        const int k0 = c * 32;
        if (c > 0) __syncthreads();   // all warps done with previous chunk

        // ---- stage A: 4 float4 per thread, split hi/lo ----
#pragma unroll
        for (int i = 0; i < 4; ++i) {
            int idx = tid + i * 256;
            int m  = idx >> 3;
            int kg = idx & 7;
            float4 xv = *(const float4*)(X + (size_t)(m0 + m) * DIN + k0 + kg * 4);
            union { __nv_bfloat16 b[4]; uint2 u; } uh, ul;
            float vv[4] = {xv.x, xv.y, xv.z, xv.w};
#pragma unroll
            for (int j = 0; j < 4; ++j) {
                __nv_bfloat16 hb = __float2bfloat16_rn(vv[j]);
                uh.b[j] = hb;
                ul.b[j] = __float2bfloat16_rn(vv[j] - __bfloat162float(hb));
            }
            *(uint2*)(sAh + m * QLD + kg * 4) = uh.u;
            *(uint2*)(sAl + m * QLD + kg * 4) = ul.u;
        }
        // ---- stage W: pre-split bf16, 2 x 16B per plane per thread ----
#pragma unroll
        for (int i = 0; i < 2; ++i) {
            int s  = tid + i * 256;
            int n  = s >> 2;
            int kg = s & 3;
            *(uint4*)(sWh + n * QLD + kg * 8) =
                *(const uint4*)(Wh + (size_t)n * 512 + k0 + kg * 8);
            *(uint4*)(sWl + n * QLD + kg * 8) =
                *(const uint4*)(Wl + (size_t)n * 512 + k0 + kg * 8);
        }
        __syncthreads();

        // ---- 2 k-steps of 16, 3 bf16 terms each ----
#pragma unroll
        for (int kc2 = 0; kc2 < 2; ++kc2) {
            const int kb = kc2 * 16;
            uint32_t ah[2][4], al[2][4];
#pragma unroll
            for (int mi = 0; mi < 2; ++mi) {
                int r0 = wm * 32 + mi * 16 + g;
                int r1 = r0 + 8;
                ah[mi][0] = *(const uint32_t*)(sAh + r0 * QLD + kb + 2 * t);
                ah[mi][1] = *(const uint32_t*)(sAh + r1 * QLD + kb + 2 * t);
                ah[mi][2] = *(const uint32_t*)(sAh + r0 * QLD + kb + 8 + 2 * t);
                ah[mi][3] = *(const uint32_t*)(sAh + r1 * QLD + kb + 8 + 2 * t);
                al[mi][0] = *(const uint32_t*)(sAl + r0 * QLD + kb + 2 * t);
                al[mi][1] = *(const uint32_t*)(sAl + r1 * QLD + kb + 2 * t);
                al[mi][2] = *(const uint32_t*)(sAl + r0 * QLD + kb + 8 + 2 * t);
                al[mi][3] = *(const uint32_t*)(sAl + r1 * QLD + kb + 8 + 2 * t);
            }
#pragma unroll
            for (int nf = 0; nf < 8; ++nf) {
                int col = wn * 64 + nf * 8 + g;
                uint32_t bh0 = *(const uint32_t*)(sWh + col * QLD + kb + 2 * t);
                uint32_t bh1 = *(const uint32_t*)(sWh + col * QLD + kb + 8 + 2 * t);
                uint32_t bl0 = *(const uint32_t*)(sWl + col * QLD + kb + 2 * t);
                uint32_t bl1 = *(const uint32_t*)(sWl + col * QLD + kb + 8 + 2 * t);
                mma_bf16(acc[0][nf], ah[0], bh0, bh1);   // hi*hi
                mma_bf16(acc[1][nf], ah[1], bh0, bh1);
                mma_bf16(acc[0][nf], ah[0], bl0, bl1);   // hi*lo
                mma_bf16(acc[1][nf], ah[1], bl0, bl1);
                mma_bf16(acc[0][nf], al[0], bh0, bh1);   // lo*hi
                mma_bf16(acc[1][nf], al[1], bh0, bh1);
            }
        }
    }

    // Epilogue: scatter to per-head layout Cb[h][bn][64].
    const int hb = (n0 >> 6) + wn;
#pragma unroll
    for (int mi = 0; mi < 2; ++mi) {
        int r0 = m0 + wm * 32 + mi * 16 + g;
        float* o0 = Cb + ((size_t)hb * BN_TOT + r0) * HDIM;
        float* o1 = Cb + ((size_t)hb * BN_TOT + r0 + 8) * HDIM;
#pragma unroll
        for (int nf = 0; nf < 8; ++nf) {
            *(float2*)(o0 + nf * 8 + 2 * t) = make_float2(acc[mi][nf][0], acc[mi][nf][1]);
            *(float2*)(o1 + nf * 8 + 2 * t) = make_float2(acc[mi][nf][2], acc[mi][nf][3]);
        }
    }
}

// ============================================================
// Mask pack: 64 int32 -> 1 uint64 bitmask per (bq, key-tile) via ballot.
// ============================================================
__global__ __launch_bounds__(256)
void pack_mask(const int* __restrict__ mask)
{
    int w = (blockIdx.x * 256 + threadIdx.x) >> 5;
    int lane = threadIdx.x & 31;
    const int* src = mask + (size_t)w * 64;
    unsigned lo = __ballot_sync(0xffffffffu, src[lane] != 0);
    unsigned hi = __ballot_sync(0xffffffffu, src[lane + 32] != 0);
    if (lane == 0)
        g_Mb[w] = ((unsigned long long)hi << 32) | (unsigned long long)lo;
}

// ============================================================
// Out projection with RAW mma.sync tf32 (R10 — measured 73us). Unchanged.
// ============================================================
#define OP_LDH 40    // 32 + 8
#define OP_LDW 136   // 128 + 8

__global__ __launch_bounds__(256, 2)
void out_proj3(const float* __restrict__ A,
               const float* __restrict__ B,
               float* __restrict__ C)
{
    __shared__ float sH[128 * OP_LDH];
    __shared__ float sW[32 * OP_LDW];

    const int tid  = threadIdx.x;
    const int w    = tid >> 5;
    const int lane = tid & 31;
    const int g    = lane >> 2;
    const int t    = lane & 3;
    const int wm   = w & 3;
    const int wn   = w >> 2;
    const int m0   = blockIdx.x * 128;
    const int n0   = blockIdx.y * 128;

    const float* At = A + (size_t)m0 * DIN;
    const float* Bt = B + n0;

    const int c4b = tid & 31;

    float acc[2][8][4];
#pragma unroll
    for (int mi = 0; mi < 2; ++mi)
#pragma unroll
        for (int nf = 0; nf < 8; ++nf)
#pragma unroll
            for (int j = 0; j < 4; ++j) acc[mi][nf][j] = 0.f;

    float4 ar[4], br[4];
#pragma unroll
    for (int i = 0; i < 4; ++i) {
        int idx = tid + i * 256;
        ar[i] = *(const float4*)(At + (size_t)(idx >> 3) * DIN + (idx & 7) * 4);
        br[i] = *(const float4*)(Bt + (size_t)((tid >> 5) + i * 8) * DIN + c4b * 4);
    }
#pragma unroll
    for (int i = 0; i < 4; ++i) {
        int idx = tid + i * 256;
        float4 xv = ar[i];
        xv.x = f2tf32_rna(xv.x); xv.y = f2tf32_rna(xv.y);
        xv.z = f2tf32_rna(xv.z); xv.w = f2tf32_rna(xv.w);
        *(float4*)(sH + (idx >> 3) * OP_LDH + (idx & 7) * 4) = xv;
        float4 bv = br[i];
        bv.x = f2tf32_rna(bv.x); bv.y = f2tf32_rna(bv.y);
        bv.z = f2tf32_rna(bv.z); bv.w = f2tf32_rna(bv.w);
        *(float4*)(sW + ((tid >> 5) + i * 8) * OP_LDW + c4b * 4) = bv;
    }
    __syncthreads();

    for (int c = 0; c < DIN / 32; ++c) {
        if (c < DIN / 32 - 1) {
            const int k0n = (c + 1) * 32;
#pragma unroll
            for (int i = 0; i < 4; ++i) {
                int idx = tid + i * 256;
                ar[i] = *(const float4*)(At + (size_t)(idx >> 3) * DIN + k0n + (idx & 7) * 4);
                br[i] = *(const float4*)(Bt + (size_t)(k0n + (tid >> 5) + i * 8) * DIN + c4b * 4);
            }
        }

#pragma unroll
        for (int kc = 0; kc < 4; ++kc) {
            uint32_t af[2][4];
#pragma unroll
            for (int mi = 0; mi < 2; ++mi) {
                const float* r0 = sH + (wm * 32 + mi * 16 + g) * OP_LDH + kc * 8;
                const float* r1 = sH + (wm * 32 + mi * 16 + g + 8) * OP_LDH + kc * 8;
                af[mi][0] = __float_as_uint(r0[t]);
                af[mi][1] = __float_as_uint(r1[t]);
                af[mi][2] = __float_as_uint(r0[t + 4]);
                af[mi][3] = __float_as_uint(r1[t + 4]);
            }
#pragma unroll
            for (int nf = 0; nf < 8; ++nf) {
                uint32_t bfr[2];
                bfr[0] = __float_as_uint(sW[(kc * 8 + t) * OP_LDW + wn * 64 + nf * 8 + g]);
                bfr[1] = __float_as_uint(sW[(kc * 8 + t + 4) * OP_LDW + wn * 64 + nf * 8 + g]);
                mma_tf32(acc[0][nf], af[0], bfr);
                mma_tf32(acc[1][nf], af[1], bfr);
            }
        }
        __syncthreads();

        if (c < DIN / 32 - 1) {
#pragma unroll
            for (int i = 0; i < 4; ++i) {
                int idx = tid + i * 256;
                float4 xv = ar[i];
                xv.x = f2tf32_rna(xv.x); xv.y = f2tf32_rna(xv.y);
                xv.z = f2tf32_rna(xv.z); xv.w = f2tf32_rna(xv.w);
                *(float4*)(sH + (idx >> 3) * OP_LDH + (idx & 7) * 4) = xv;
                float4 bv = br[i];
                bv.x = f2tf32_rna(bv.x); bv.y = f2tf32_rna(bv.y);
                bv.z = f2tf32_rna(bv.z); bv.w = f2tf32_rna(bv.w);
                *(float4*)(sW + ((tid >> 5) + i * 8) * OP_LDW + c4b * 4) = bv;
            }
            __syncthreads();
        }
    }

#pragma unroll
    for (int mi = 0; mi < 2; ++mi) {
        float* r0 = C + (size_t)(m0 + wm * 32 + mi * 16 + g) * DIN + n0 + wn * 64;
        float* r1 = C + (size_t)(m0 + wm * 32 + mi * 16 + g + 8) * DIN + n0 + wn * 64;
#pragma unroll
        for (int nf = 0; nf < 8; ++nf) {
            *(float2*)(r0 + nf * 8 + 2 * t) = make_float2(acc[mi][nf][0], acc[mi][nf][1]);
            *(float2*)(r1 + nf * 8 + 2 * t) = make_float2(acc[mi][nf][2], acc[mi][nf][3]);
        }
    }
}

// ============================================================
// FA2-style flash attention, raw mma.sync tf32, HW EX2 (R10 — measured good).
// ============================================================
#define LDK 68
#define LDV 72
#define LDP 68
#define ATTN_SMEM ((64 * LDK + 64 * LDV + 128 * LDP) * 4)

__global__ __launch_bounds__(256, 2)
void attn_mma()
{
    extern __shared__ float sm[];
    float* sK = sm;
    float* sV = sK + 64 * LDK;
    float* sP = sV + 64 * LDV;

    const int tid  = threadIdx.x;
    const int w    = tid >> 5;
    const int lane = tid & 31;
    const int g    = lane >> 2;
    const int t    = lane & 3;
    const int q0   = blockIdx.x * 128;
    const int b    = blockIdx.y;
    const int h    = blockIdx.z;

    const float* Qg = g_Q + ((size_t)(h * BATCH + b) * NQ + q0) * HDIM;
    const float* Kg = g_K + (size_t)(h * BATCH + b) * NK * HDIM;
    const float* Vg = g_V + (size_t)(h * BATCH + b) * NK * HDIM;

    const float qscale = NORM_F * LOG2E;
    uint32_t qf[8][4];
#pragma unroll
    for (int kc = 0; kc < 8; ++kc) {
        const float* r0 = Qg + (size_t)(w * 16 + g) * HDIM + kc * 8;
        const float* r1 = Qg + (size_t)(w * 16 + g + 8) * HDIM + kc * 8;
        qf[kc][0] = __float_as_uint(f2tf32_rna(r0[t] * qscale));
        qf[kc][1] = __float_as_uint(f2tf32_rna(r1[t] * qscale));
        qf[kc][2] = __float_as_uint(f2tf32_rna(r0[t + 4] * qscale));
        qf[kc][3] = __float_as_uint(f2tf32_rna(r1[t + 4] * qscale));
    }

    float oacc[8][4];
#pragma unroll
    for (int nt = 0; nt < 8; ++nt)
#pragma unroll
        for (int j = 0; j < 4; ++j) oacc[nt][j] = 0.f;
    float m0 = -1e30f, m1 = -1e30f;
    float l0 = 0.f, l1 = 0.f;

    const unsigned long long* mb_row0 = g_Mb + ((size_t)b * NQ + q0 + w * 16 + g) * (NK / 64);
    const unsigned long long* mb_row1 = mb_row0 + 8 * (NK / 64);
    float* sPw = sP + (w * 16) * LDP;

    for (int kt = 0; kt < NK / 64; ++kt) {
        __syncthreads();
#pragma unroll
        for (int i = 0; i < 4; ++i) {
            int idx = tid + i * 256;
            int r  = idx >> 4;
            int c4 = idx & 15;
            float4 kv = *(const float4*)(Kg + (size_t)(kt * 64 + r) * HDIM + c4 * 4);
            kv.x = f2tf32_rna(kv.x); kv.y = f2tf32_rna(kv.y);
            kv.z = f2tf32_rna(kv.z); kv.w = f2tf32_rna(kv.w);
            *(float4*)(sK + r * LDK + c4 * 4) = kv;
            float4 vv = *(const float4*)(Vg + (size_t)(kt * 64 + r) * HDIM + c4 * 4);
            vv.x = f2tf32_rna(vv.x); vv.y = f2tf32_rna(vv.y);
            vv.z = f2tf32_rna(vv.z); vv.w = f2tf32_rna(vv.w);
            *(float4*)(sV + r * LDV + c4 * 4) = vv;
        }
        __syncthreads();

        float sacc[8][4];
#pragma unroll
        for (int nt = 0; nt < 8; ++nt) {
#pragma unroll
            for (int j = 0; j < 4; ++j) sacc[nt][j] = 0.f;
#pragma unroll
            for (int kc = 0; kc < 8; ++kc) {
                uint32_t bfr[2];
                const float* kb = sK + (nt * 8 + g) * LDK + kc * 8;
                bfr[0] = __float_as_uint(kb[t]);
                bfr[1] = __float_as_uint(kb[t + 4]);
                mma_tf32(sacc[nt], qf[kc], bfr);
            }
        }

        unsigned long long mb0 = mb_row0[kt];
        unsigned long long mb1 = mb_row1[kt];
        float tmax0 = -1e30f, tmax1 = -1e30f;
#pragma unroll
        for (int nt = 0; nt < 8; ++nt) {
            int c0 = nt * 8 + 2 * t, c1 = c0 + 1;
            if ((mb0 >> c0) & 1ull) sacc[nt][0] = -1e30f;
            if ((mb0 >> c1) & 1ull) sacc[nt][1] = -1e30f;
            if ((mb1 >> c0) & 1ull) sacc[nt][2] = -1e30f;
            if ((mb1 >> c1) & 1ull) sacc[nt][3] = -1e30f;
            tmax0 = fmaxf(tmax0, fmaxf(sacc[nt][0], sacc[nt][1]));
            tmax1 = fmaxf(tmax1, fmaxf(sacc[nt][2], sacc[nt][3]));
        }
        tmax0 = fmaxf(tmax0, __shfl_xor_sync(0xffffffffu, tmax0, 1));
        tmax0 = fmaxf(tmax0, __shfl_xor_sync(0xffffffffu, tmax0, 2));
        tmax1 = fmaxf(tmax1, __shfl_xor_sync(0xffffffffu, tmax1, 1));
        tmax1 = fmaxf(tmax1, __shfl_xor_sync(0xffffffffu, tmax1, 2));

        float mn0 = fmaxf(m0, tmax0);
        float mn1 = fmaxf(m1, tmax1);
        float sc0 = ex2_approx(m0 - mn0);
        float sc1 = ex2_approx(m1 - mn1);
        m0 = mn0; m1 = mn1;

        float ps0 = 0.f, ps1 = 0.f;
#pragma unroll
        for (int nt = 0; nt < 8; ++nt) {
            float p0 = ex2_approx(sacc[nt][0] - mn0);
            float p1 = ex2_approx(sacc[nt][1] - mn0);
            float p2 = ex2_approx(sacc[nt][2] - mn1);
            float p3 = ex2_approx(sacc[nt][3] - mn1);
            ps0 += p0 + p1;
            ps1 += p2 + p3;
            float2 lo = make_float2(f2tf32_rna(p0), f2tf32_rna(p1));
            float2 hi = make_float2(f2tf32_rna(p2), f2tf32_rna(p3));
            *(float2*)(sPw + g * LDP + nt * 8 + 2 * t) = lo;
            *(float2*)(sPw + (g + 8) * LDP + nt * 8 + 2 * t) = hi;
        }
        ps0 += __shfl_xor_sync(0xffffffffu, ps0, 1);
        ps0 += __shfl_xor_sync(0xffffffffu, ps0, 2);
        ps1 += __shfl_xor_sync(0xffffffffu, ps1, 1);
        ps1 += __shfl_xor_sync(0xffffffffu, ps1, 2);
        l0 = l0 * sc0 + ps0;
        l1 = l1 * sc1 + ps1;

#pragma unroll
        for (int nt = 0; nt < 8; ++nt) {
            oacc[nt][0] *= sc0; oacc[nt][1] *= sc0;
            oacc[nt][2] *= sc1; oacc[nt][3] *= sc1;
        }
        __syncwarp();

#pragma unroll
        for (int kc = 0; kc < 8; ++kc) {
            uint32_t pa[4];
            const float* p0r = sPw + g * LDP + kc * 8;
            const float* p1r = sPw + (g + 8) * LDP + kc * 8;
            pa[0] = __float_as_uint(p0r[t]);
            pa[1] = __float_as_uint(p1r[t]);
            pa[2] = __float_as_uint(p0r[t + 4]);
            pa[3] = __float_as_uint(p1r[t + 4]);
#pragma unroll
            for (int nt = 0; nt < 8; ++nt) {
                uint32_t bfr[2];
                bfr[0] = __float_as_uint(sV[(kc * 8 + t) * LDV + nt * 8 + g]);
                bfr[1] = __float_as_uint(sV[(kc * 8 + t + 4) * LDV + nt * 8 + g]);
                mma_tf32(oacc[nt], pa, bfr);
            }
        }
        __syncwarp();
    }

    float inv0 = (l0 > 0.f) ? (1.f / l0) : 0.f;
    float inv1 = (l1 > 0.f) ? (1.f / l1) : 0.f;
    float* o0 = g_H + ((size_t)(b * NQ + q0 + w * 16 + g)) * DIN + h * HDIM;
    float* o1 = g_H + ((size_t)(b * NQ + q0 + w * 16 + g + 8)) * DIN + h * HDIM;
#pragma unroll
    for (int nt = 0; nt < 8; ++nt) {
        *(float2*)(o0 + nt * 8 + 2 * t) = make_float2(oacc[nt][0] * inv0, oacc[nt][1] * inv0);
        *(float2*)(o1 + nt * 8 + 2 * t) = make_float2(oacc[nt][2] * inv1, oacc[nt][3] * inv1);
    }
}

// ============================================================
extern "C" void kernel_launch(void* const* d_in, const int* in_sizes, int n_in,
                              void* d_out, int out_size)
{
    const float* q  = (const float*)d_in[0];
    const float* k  = (const float*)d_in[1];
    const float* v  = (const float*)d_in[2];
    const int*   mask = (const int*)d_in[3];
    const float* Wq = (const float*)d_in[4];
    const float* Wk = (const float*)d_in[5];
    const float* Wv = (const float*)d_in[6];
    const float* Wo = (const float*)d_in[7];
    float* out = (float*)d_out;

    float *pH;
    cudaGetSymbolAddress((void**)&pH, g_H);

    static bool attr_set = false;
    if (!attr_set) {
        cudaFuncSetAttribute(attn_mma,
                             cudaFuncAttributeMaxDynamicSharedMemorySize,
                             ATTN_SMEM);
        attr_set = true;
    }

    // Split + transpose QKV weights to bf16 hi/lo planes (3 MB)
    w_prep<<<(3 * 512 * 512) / 256, 256>>>(Wq, Wk, Wv);

    // QKV projections: bf16x3 tensor-core GEMM (error ~2^-16)
    qkv_bf<<<dim3(BN_TOT / 128, DIN / 128, 3), 256>>>(q, k, v);

    // Pack mask to bitmasks
    pack_mask<<<(BN_TOT * (NK / 64)) / 8, 256>>>(mask);

    // Flash attention (raw mma.sync tf32, register softmax, HW EX2)
    attn_mma<<<dim3(NQ / 128, BATCH, NHEADS), 256, ATTN_SMEM>>>();

    // Output projection: raw mma.sync tf32
    out_proj3<<<dim3(BN_TOT / 128, DIN / 128), 256>>>(pH, Wo, out);
}

// round 13
// speedup vs baseline: 2.4308x; 1.0733x over previous
#include <cuda_runtime.h>
#include <cuda_bf16.h>
#include <cstdint>

// Problem constants
#define BATCH   16
#define NQ      1024
#define NK      1024
#define DIN     512
#define NHEADS  8
#define HDIM    64
#define BN_TOT  (BATCH * NQ)       // 16384
#define NORM_F  0.125f             // 1/sqrt(64)
#define LOG2E   1.4426950408889634f

// -------- scratch (device globals: allocation-free) --------
// g_Q holds Q pre-scaled by NORM*LOG2E and tf32-rounded; g_K/g_V tf32-rounded.
__device__ float g_Q[(size_t)NHEADS * BN_TOT * HDIM];   // [h][bn][64]
__device__ float g_K[(size_t)NHEADS * BN_TOT * HDIM];
__device__ float g_V[(size_t)NHEADS * BN_TOT * HDIM];
__device__ float g_H[(size_t)BN_TOT * DIN];             // [bn][h*64+v], tf32-rounded
__device__ unsigned long long g_Mb[(size_t)BN_TOT * (NK / 64)];  // permuted mask bits
// bf16 hi/lo split of QKV weights, layout [op][n_global(512)][k(512)]
__device__ __nv_bfloat16 g_Wbh[(size_t)3 * 512 * 512];
__device__ __nv_bfloat16 g_Wbl[(size_t)3 * 512 * 512];

__device__ __forceinline__ float f2tf32_rna(float x) {
    uint32_t r;
    asm("cvt.rna.tf32.f32 %0, %1;" : "=r"(r) : "f"(x));
    return __uint_as_float(r);
}

// Hardware EX2 (single MUFU op)
__device__ __forceinline__ float ex2_approx(float x) {
    float r;
    asm("ex2.approx.f32 %0, %1;" : "=f"(r) : "f"(x));
    return r;
}

// m16n8k8 tf32 mma (g=lane>>2, t=lane&3):
//   A: a0(g,t) a1(g+8,t) a2(g,t+4) a3(g+8,t+4)
//   B: b0(k=t,n=g) b1(k=t+4,n=g)
//   C: c0(g,2t) c1(g,2t+1) c2(g+8,2t) c3(g+8,2t+1)
__device__ __forceinline__ void mma_tf32(float* c, const uint32_t* a, const uint32_t* b) {
    asm volatile(
        "mma.sync.aligned.m16n8k8.row.col.f32.tf32.tf32.f32 "
        "{%0,%1,%2,%3}, {%4,%5,%6,%7}, {%8,%9}, {%0,%1,%2,%3};"
        : "+f"(c[0]), "+f"(c[1]), "+f"(c[2]), "+f"(c[3])
        : "r"(a[0]), "r"(a[1]), "r"(a[2]), "r"(a[3]), "r"(b[0]), "r"(b[1]));
}

// m16n8k16 bf16 mma. Each 32-bit reg = 2 bf16 along K.
__device__ __forceinline__ void mma_bf16(float* c, const uint32_t* a,
                                         uint32_t b0, uint32_t b1) {
    asm volatile(
        "mma.sync.aligned.m16n8k16.row.col.f32.bf16.bf16.f32 "
        "{%0,%1,%2,%3}, {%4,%5,%6,%7}, {%8,%9}, {%0,%1,%2,%3};"
        : "+f"(c[0]), "+f"(c[1]), "+f"(c[2]), "+f"(c[3])
        : "r"(a[0]), "r"(a[1]), "r"(a[2]), "r"(a[3]), "r"(b0), "r"(b1));
}

// ============================================================
// W prep: split QKV weights to bf16 hi/lo, transposed to [op][n][k].
// ============================================================
__global__ __launch_bounds__(256)
void w_prep(const float* __restrict__ Wq,
            const float* __restrict__ Wk,
            const float* __restrict__ Wv)
{
    size_t idx = (size_t)blockIdx.x * 256 + threadIdx.x;   // [op][n][k]
    int k  = idx & 511;
    int n  = (idx >> 9) & 511;
    int op = (int)(idx >> 18);
    const float* W = (op == 0 ? Wq : (op == 1 ? Wk : Wv));
    float w = W[(size_t)((n >> 6) * 512 + k) * 64 + (n & 63)];
    __nv_bfloat16 hi = __float2bfloat16_rn(w);
    __nv_bfloat16 lo = __float2bfloat16_rn(w - __bfloat162float(hi));
    g_Wbh[idx] = hi;
    g_Wbl[idx] = lo;
}

// ============================================================
// QKV projection via bf16x3 split tensor-core GEMM (R12 core, measured good).
// R13: epilogue pre-rounds outputs to tf32; Q additionally pre-scaled by
// NORM*LOG2E. (Rounding relocated from attn staging — error-identical.)
// grid = (128 m-tiles, 4 n-tiles, 3 ops)
// ============================================================
#define QLD 40

__global__ __launch_bounds__(256, 2)
void qkv_bf(const float* __restrict__ q,
            const float* __restrict__ k,
            const float* __restrict__ v)
{
    __shared__ __nv_bfloat16 sAh[128 * QLD];
    __shared__ __nv_bfloat16 sAl[128 * QLD];
    __shared__ __nv_bfloat16 sWh[128 * QLD];
    __shared__ __nv_bfloat16 sWl[128 * QLD];

    const int tid  = threadIdx.x;
    const int w    = tid >> 5;
    const int lane = tid & 31;
    const int g    = lane >> 2;
    const int t    = lane & 3;
    const int wm   = w & 3;
    const int wn   = w >> 2;
    const int op   = blockIdx.z;
    const int m0   = blockIdx.x * 128;
    const int n0   = blockIdx.y * 128;

    const float* X = (op == 0 ? q : (op == 1 ? k : v));
    float* Cb      = (op == 0 ? g_Q : (op == 1 ? g_K : g_V));
    const __nv_bfloat16* Wh = g_Wbh + ((size_t)op * 512 + n0) * 512;
    const __nv_bfloat16* Wl = g_Wbl + ((size_t)op * 512 + n0) * 512;

    float acc[2][8][4];
#pragma unroll
    for (int mi = 0; mi < 2; ++mi)
#pragma unroll
        for (int nf = 0; nf < 8; ++nf)
#pragma unroll
            for (int j = 0; j < 4; ++j) acc[mi][nf][j] = 0.f;

    for (int c = 0; c < DIN / 32; ++c) {
        const int k0 = c * 32;
        if (c > 0) __syncthreads();

        // ---- stage A: 4 float4 per thread, split hi/lo ----
#pragma unroll
        for (int i = 0; i < 4; ++i) {
            int idx = tid + i * 256;
            int m  = idx >> 3;
            int kg = idx & 7;
            float4 xv = *(const float4*)(X + (size_t)(m0 + m) * DIN + k0 + kg * 4);
            union { __nv_bfloat16 b[4]; uint2 u; } uh, ul;
            float vv[4] = {xv.x, xv.y, xv.z, xv.w};
#pragma unroll
            for (int j = 0; j < 4; ++j) {
                __nv_bfloat16 hb = __float2bfloat16_rn(vv[j]);
                uh.b[j] = hb;
                ul.b[j] = __float2bfloat16_rn(vv[j] - __bfloat162float(hb));
            }
            *(uint2*)(sAh + m * QLD + kg * 4) = uh.u;
            *(uint2*)(sAl + m * QLD + kg * 4) = ul.u;
        }
        // ---- stage W: pre-split bf16, 2 x 16B per plane per thread ----
#pragma unroll
        for (int i = 0; i < 2; ++i) {
            int s  = tid + i * 256;
            int n  = s >> 2;
            int kg = s & 3;
            *(uint4*)(sWh + n * QLD + kg * 8) =
                *(const uint4*)(Wh + (size_t)n * 512 + k0 + kg * 8);
            *(uint4*)(sWl + n * QLD + kg * 8) =
                *(const uint4*)(Wl + (size_t)n * 512 + k0 + kg * 8);
        }
        __syncthreads();

        // ---- 2 k-steps of 16, 3 bf16 terms each ----
#pragma unroll
        for (int kc2 = 0; kc2 < 2; ++kc2) {
            const int kb = kc2 * 16;
            uint32_t ah[2][4], al[2][4];
#pragma unroll
            for (int mi = 0; mi < 2; ++mi) {
                int r0 = wm * 32 + mi * 16 + g;
                int r1 = r0 + 8;
                ah[mi][0] = *(const uint32_t*)(sAh + r0 * QLD + kb + 2 * t);
                ah[mi][1] = *(const uint32_t*)(sAh + r1 * QLD + kb + 2 * t);
                ah[mi][2] = *(const uint32_t*)(sAh + r0 * QLD + kb + 8 + 2 * t);
                ah[mi][3] = *(const uint32_t*)(sAh + r1 * QLD + kb + 8 + 2 * t);
                al[mi][0] = *(const uint32_t*)(sAl + r0 * QLD + kb + 2 * t);
                al[mi][1] = *(const uint32_t*)(sAl + r1 * QLD + kb + 2 * t);
                al[mi][2] = *(const uint32_t*)(sAl + r0 * QLD + kb + 8 + 2 * t);
                al[mi][3] = *(const uint32_t*)(sAl + r1 * QLD + kb + 8 + 2 * t);
            }
#pragma unroll
            for (int nf = 0; nf < 8; ++nf) {
                int col = wn * 64 + nf * 8 + g;
                uint32_t bh0 = *(const uint32_t*)(sWh + col * QLD + kb + 2 * t);
                uint32_t bh1 = *(const uint32_t*)(sWh + col * QLD + kb + 8 + 2 * t);
                uint32_t bl0 = *(const uint32_t*)(sWl + col * QLD + kb + 2 * t);
                uint32_t bl1 = *(const uint32_t*)(sWl + col * QLD + kb + 8 + 2 * t);
                mma_bf16(acc[0][nf], ah[0], bh0, bh1);   // hi*hi
                mma_bf16(acc[1][nf], ah[1], bh0, bh1);
                mma_bf16(acc[0][nf], ah[0], bl0, bl1);   // hi*lo
                mma_bf16(acc[1][nf], ah[1], bl0, bl1);
                mma_bf16(acc[0][nf], al[0], bh0, bh1);   // lo*hi
                mma_bf16(acc[1][nf], al[1], bh0, bh1);
            }
        }
    }

    // Epilogue: scatter to per-head layout Cb[h][bn][64], pre-rounded tf32.
    // Q additionally pre-scaled by NORM*LOG2E (attn consumes it directly).
    const float osc = (op == 0) ? (NORM_F * LOG2E) : 1.0f;
    const int hb = (n0 >> 6) + wn;
#pragma unroll
    for (int mi = 0; mi < 2; ++mi) {
        int r0 = m0 + wm * 32 + mi * 16 + g;
        float* o0 = Cb + ((size_t)hb * BN_TOT + r0) * HDIM;
        float* o1 = Cb + ((size_t)hb * BN_TOT + r0 + 8) * HDIM;
#pragma unroll
        for (int nf = 0; nf < 8; ++nf) {
            *(float2*)(o0 + nf * 8 + 2 * t) =
                make_float2(f2tf32_rna(acc[mi][nf][0] * osc), f2tf32_rna(acc[mi][nf][1] * osc));
            *(float2*)(o1 + nf * 8 + 2 * t) =
                make_float2(f2tf32_rna(acc[mi][nf][2] * osc), f2tf32_rna(acc[mi][nf][3] * osc));
        }
    }
}

// ============================================================
// Mask pack, PERMUTED layout: bit position pos = t*16 + nt*2 + par for
// source column c = nt*8 + 2t + par. Thread t in attn then extracts its
// 16-bit chunk with ONE 64-bit shift and tests constant bit positions.
// Lane L of lo-ballot reads c(L) with t = L>>4 (0..1); hi-ballot t+2.
// ============================================================
__global__ __launch_bounds__(256)
void pack_mask(const int* __restrict__ mask)
{
    int w = (blockIdx.x * 256 + threadIdx.x) >> 5;   // (row, tile) word
    int L = threadIdx.x & 31;
    const int* src = mask + (size_t)w * 64;
    int t_lo = L >> 4;
    int nt   = (L >> 1) & 7;
    int par  = L & 1;
    int c_lo = nt * 8 + 2 * t_lo + par;          // t in {0,1}
    int c_hi = nt * 8 + 2 * (t_lo + 2) + par;    // t in {2,3}
    unsigned lo = __ballot_sync(0xffffffffu, src[c_lo] != 0);
    unsigned hi = __ballot_sync(0xffffffffu, src[c_hi] != 0);
    if (L == 0)
        g_Mb[w] = ((unsigned long long)hi << 32) | (unsigned long long)lo;
}

// ============================================================
// Out projection with RAW mma.sync tf32 (R10 core — measured 73us).
// R13: sH staging drops cvt (H pre-rounded by attn epilogue).
// ============================================================
#define OP_LDH 40    // 32 + 8
#define OP_LDW 136   // 128 + 8

__global__ __launch_bounds__(256, 2)
void out_proj3(const float* __restrict__ A,
               const float* __restrict__ B,
               float* __restrict__ C)
{
    __shared__ float sH[128 * OP_LDH];
    __shared__ float sW[32 * OP_LDW];

    const int tid  = threadIdx.x;
    const int w    = tid >> 5;
    const int lane = tid & 31;
    const int g    = lane >> 2;
    const int t    = lane & 3;
    const int wm   = w & 3;
    const int wn   = w >> 2;
    const int m0   = blockIdx.x * 128;
    const int n0   = blockIdx.y * 128;

    const float* At = A + (size_t)m0 * DIN;
    const float* Bt = B + n0;
    const int c4b = tid & 31;

    float acc[2][8][4];
#pragma unroll
    for (int mi = 0; mi < 2; ++mi)
#pragma unroll
        for (int nf = 0; nf < 8; ++nf)
#pragma unroll
            for (int j = 0; j < 4; ++j) acc[mi][nf][j] = 0.f;

    float4 ar[4], br[4];
#pragma unroll
    for (int i = 0; i < 4; ++i) {
        int idx = tid + i * 256;
        ar[i] = *(const float4*)(At + (size_t)(idx >> 3) * DIN + (idx & 7) * 4);
        br[i] = *(const float4*)(Bt + (size_t)((tid >> 5) + i * 8) * DIN + c4b * 4);
    }
#pragma unroll
    for (int i = 0; i < 4; ++i) {
        int idx = tid + i * 256;
        *(float4*)(sH + (idx >> 3) * OP_LDH + (idx & 7) * 4) = ar[i];   // pre-rounded
        float4 bv = br[i];
        bv.x = f2tf32_rna(bv.x); bv.y = f2tf32_rna(bv.y);
        bv.z = f2tf32_rna(bv.z); bv.w = f2tf32_rna(bv.w);
        *(float4*)(sW + ((tid >> 5) + i * 8) * OP_LDW + c4b * 4) = bv;
    }
    __syncthreads();

    for (int c = 0; c < DIN / 32; ++c) {
        if (c < DIN / 32 - 1) {
            const int k0n = (c + 1) * 32;
#pragma unroll
            for (int i = 0; i < 4; ++i) {
                int idx = tid + i * 256;
                ar[i] = *(const float4*)(At + (size_t)(idx >> 3) * DIN + k0n + (idx & 7) * 4);
                br[i] = *(const float4*)(Bt + (size_t)(k0n + (tid >> 5) + i * 8) * DIN + c4b * 4);
            }
        }

#pragma unroll
        for (int kc = 0; kc < 4; ++kc) {
            uint32_t af[2][4];
#pragma unroll
            for (int mi = 0; mi < 2; ++mi) {
                const float* r0 = sH + (wm * 32 + mi * 16 + g) * OP_LDH + kc * 8;
                const float* r1 = sH + (wm * 32 + mi * 16 + g + 8) * OP_LDH + kc * 8;
                af[mi][0] = __float_as_uint(r0[t]);
                af[mi][1] = __float_as_uint(r1[t]);
                af[mi][2] = __float_as_uint(r0[t + 4]);
                af[mi][3] = __float_as_uint(r1[t + 4]);
            }
#pragma unroll
            for (int nf = 0; nf < 8; ++nf) {
                uint32_t bfr[2];
                bfr[0] = __float_as_uint(sW[(kc * 8 + t) * OP_LDW + wn * 64 + nf * 8 + g]);
                bfr[1] = __float_as_uint(sW[(kc * 8 + t + 4) * OP_LDW + wn * 64 + nf * 8 + g]);
                mma_tf32(acc[0][nf], af[0], bfr);
                mma_tf32(acc[1][nf], af[1], bfr);
            }
        }
        __syncthreads();

        if (c < DIN / 32 - 1) {
#pragma unroll
            for (int i = 0; i < 4; ++i) {
                int idx = tid + i * 256;
                *(float4*)(sH + (idx >> 3) * OP_LDH + (idx & 7) * 4) = ar[i];
                float4 bv = br[i];
                bv.x = f2tf32_rna(bv.x); bv.y = f2tf32_rna(bv.y);
                bv.z = f2tf32_rna(bv.z); bv.w = f2tf32_rna(bv.w);
                *(float4*)(sW + ((tid >> 5) + i * 8) * OP_LDW + c4b * 4) = bv;
            }
            __syncthreads();
        }
    }

#pragma unroll
    for (int mi = 0; mi < 2; ++mi) {
        float* r0 = C + (size_t)(m0 + wm * 32 + mi * 16 + g) * DIN + n0 + wn * 64;
        float* r1 = C + (size_t)(m0 + wm * 32 + mi * 16 + g + 8) * DIN + n0 + wn * 64;
#pragma unroll
        for (int nf = 0; nf < 8; ++nf) {
            *(float2*)(r0 + nf * 8 + 2 * t) = make_float2(acc[mi][nf][0], acc[mi][nf][1]);
            *(float2*)(r1 + nf * 8 + 2 * t) = make_float2(acc[mi][nf][2], acc[mi][nf][3]);
        }
    }
}

// ============================================================
// FA2-style flash attention, raw mma.sync tf32, HW EX2.
// R13: Q/K/V arrive pre-rounded (Q pre-scaled) -> staging is pure copies;
// mask uses permuted packing -> 1 shift + constant-bit tests per row/tile.
// ============================================================
#define LDK 68
#define LDV 72
#define LDP 68
#define ATTN_SMEM ((64 * LDK + 64 * LDV + 128 * LDP) * 4)

__global__ __launch_bounds__(256, 2)
void attn_mma()
{
    extern __shared__ float sm[];
    float* sK = sm;
    float* sV = sK + 64 * LDK;
    float* sP = sV + 64 * LDV;

    const int tid  = threadIdx.x;
    const int w    = tid >> 5;
    const int lane = tid & 31;
    const int g    = lane >> 2;
    const int t    = lane & 3;
    const int q0   = blockIdx.x * 128;
    const int b    = blockIdx.y;
    const int h    = blockIdx.z;

    const float* Qg = g_Q + ((size_t)(h * BATCH + b) * NQ + q0) * HDIM;
    const float* Kg = g_K + (size_t)(h * BATCH + b) * NK * HDIM;
    const float* Vg = g_V + (size_t)(h * BATCH + b) * NK * HDIM;

    // Q already scaled + tf32-rounded: raw bit loads.
    uint32_t qf[8][4];
#pragma unroll
    for (int kc = 0; kc < 8; ++kc) {
        const uint32_t* r0 = (const uint32_t*)(Qg + (size_t)(w * 16 + g) * HDIM + kc * 8);
        const uint32_t* r1 = (const uint32_t*)(Qg + (size_t)(w * 16 + g + 8) * HDIM + kc * 8);
        qf[kc][0] = r0[t];
        qf[kc][1] = r1[t];
        qf[kc][2] = r0[t + 4];
        qf[kc][3] = r1[t + 4];
    }

    float oacc[8][4];
#pragma unroll
    for (int nt = 0; nt < 8; ++nt)
#pragma unroll
        for (int j = 0; j < 4; ++j) oacc[nt][j] = 0.f;
    float m0 = -1e30f, m1 = -1e30f;
    float l0 = 0.f, l1 = 0.f;

    const unsigned long long* mb_row0 = g_Mb + ((size_t)b * NQ + q0 + w * 16 + g) * (NK / 64);
    const unsigned long long* mb_row1 = mb_row0 + 8 * (NK / 64);
    float* sPw = sP + (w * 16) * LDP;
    const int tsh = t * 16;

    for (int kt = 0; kt < NK / 64; ++kt) {
        __syncthreads();
        // Stage K/V tiles: pure vector copies (pre-rounded upstream).
#pragma unroll
        for (int i = 0; i < 4; ++i) {
            int idx = tid + i * 256;
            int r  = idx >> 4;
            int c4 = idx & 15;
            *(float4*)(sK + r * LDK + c4 * 4) =
                *(const float4*)(Kg + (size_t)(kt * 64 + r) * HDIM + c4 * 4);
            *(float4*)(sV + r * LDV + c4 * 4) =
                *(const float4*)(Vg + (size_t)(kt * 64 + r) * HDIM + c4 * 4);
        }
        __syncthreads();

        float sacc[8][4];
#pragma unroll
        for (int nt = 0; nt < 8; ++nt) {
#pragma unroll
            for (int j = 0; j < 4; ++j) sacc[nt][j] = 0.f;
#pragma unroll
            for (int kc = 0; kc < 8; ++kc) {
                uint32_t bfr[2];
                const float* kb = sK + (nt * 8 + g) * LDK + kc * 8;
                bfr[0] = __float_as_uint(kb[t]);
                bfr[1] = __float_as_uint(kb[t + 4]);
                mma_tf32(sacc[nt], qf[kc], bfr);
            }
        }

        // Permuted mask: thread t's bits at [t*16 + nt*2 + par].
        uint32_t ch0 = (uint32_t)(mb_row0[kt] >> tsh) & 0xffffu;
        uint32_t ch1 = (uint32_t)(mb_row1[kt] >> tsh) & 0xffffu;
        float tmax0 = -1e30f, tmax1 = -1e30f;
#pragma unroll
        for (int nt = 0; nt < 8; ++nt) {
            if (ch0 & (1u << (2 * nt)))     sacc[nt][0] = -1e30f;
            if (ch0 & (2u << (2 * nt)))     sacc[nt][1] = -1e30f;
            if (ch1 & (1u << (2 * nt)))     sacc[nt][2] = -1e30f;
            if (ch1 & (2u << (2 * nt)))     sacc[nt][3] = -1e30f;
            tmax0 = fmaxf(tmax0, fmaxf(sacc[nt][0], sacc[nt][1]));
            tmax1 = fmaxf(tmax1, fmaxf(sacc[nt][2], sacc[nt][3]));
        }
        tmax0 = fmaxf(tmax0, __shfl_xor_sync(0xffffffffu, tmax0, 1));
        tmax0 = fmaxf(tmax0, __shfl_xor_sync(0xffffffffu, tmax0, 2));
        tmax1 = fmaxf(tmax1, __shfl_xor_sync(0xffffffffu, tmax1, 1));
        tmax1 = fmaxf(tmax1, __shfl_xor_sync(0xffffffffu, tmax1, 2));

        float mn0 = fmaxf(m0, tmax0);
        float mn1 = fmaxf(m1, tmax1);
        float sc0 = ex2_approx(m0 - mn0);
        float sc1 = ex2_approx(m1 - mn1);
        m0 = mn0; m1 = mn1;

        float ps0 = 0.f, ps1 = 0.f;
#pragma unroll
        for (int nt = 0; nt < 8; ++nt) {
            float p0 = ex2_approx(sacc[nt][0] - mn0);
            float p1 = ex2_approx(sacc[nt][1] - mn0);
            float p2 = ex2_approx(sacc[nt][2] - mn1);
            float p3 = ex2_approx(sacc[nt][3] - mn1);
            ps0 += p0 + p1;
            ps1 += p2 + p3;
            float2 lo = make_float2(f2tf32_rna(p0), f2tf32_rna(p1));
            float2 hi = make_float2(f2tf32_rna(p2), f2tf32_rna(p3));
            *(float2*)(sPw + g * LDP + nt * 8 + 2 * t) = lo;
            *(float2*)(sPw + (g + 8) * LDP + nt * 8 + 2 * t) = hi;
        }
        ps0 += __shfl_xor_sync(0xffffffffu, ps0, 1);
        ps0 += __shfl_xor_sync(0xffffffffu, ps0, 2);
        ps1 += __shfl_xor_sync(0xffffffffu, ps1, 1);
        ps1 += __shfl_xor_sync(0xffffffffu, ps1, 2);
        l0 = l0 * sc0 + ps0;
        l1 = l1 * sc1 + ps1;

#pragma unroll
        for (int nt = 0; nt < 8; ++nt) {
            oacc[nt][0] *= sc0; oacc[nt][1] *= sc0;
            oacc[nt][2] *= sc1; oacc[nt][3] *= sc1;
        }
        __syncwarp();

#pragma unroll
        for (int kc = 0; kc < 8; ++kc) {
            uint32_t pa[4];
            const float* p0r = sPw + g * LDP + kc * 8;
            const float* p1r = sPw + (g + 8) * LDP + kc * 8;
            pa[0] = __float_as_uint(p0r[t]);
            pa[1] = __float_as_uint(p1r[t]);
            pa[2] = __float_as_uint(p0r[t + 4]);
            pa[3] = __float_as_uint(p1r[t + 4]);
#pragma unroll
            for (int nt = 0; nt < 8; ++nt) {
                uint32_t bfr[2];
                bfr[0] = __float_as_uint(sV[(kc * 8 + t) * LDV + nt * 8 + g]);
                bfr[1] = __float_as_uint(sV[(kc * 8 + t + 4) * LDV + nt * 8 + g]);
                mma_tf32(oacc[nt], pa, bfr);
            }
        }
        __syncwarp();
    }

    // Normalize, pre-round to tf32 (out_proj consumes directly), write g_H.
    float inv0 = (l0 > 0.f) ? (1.f / l0) : 0.f;
    float inv1 = (l1 > 0.f) ? (1.f / l1) : 0.f;
    float* o0 = g_H + ((size_t)(b * NQ + q0 + w * 16 + g)) * DIN + h * HDIM;
    float* o1 = g_H + ((size_t)(b * NQ + q0 + w * 16 + g + 8)) * DIN + h * HDIM;
#pragma unroll
    for (int nt = 0; nt < 8; ++nt) {
        *(float2*)(o0 + nt * 8 + 2 * t) =
            make_float2(f2tf32_rna(oacc[nt][0] * inv0), f2tf32_rna(oacc[nt][1] * inv0));
        *(float2*)(o1 + nt * 8 + 2 * t) =
            make_float2(f2tf32_rna(oacc[nt][2] * inv1), f2tf32_rna(oacc[nt][3] * inv1));
    }
}

// ============================================================
extern "C" void kernel_launch(void* const* d_in, const int* in_sizes, int n_in,
                              void* d_out, int out_size)
{
    const float* q  = (const float*)d_in[0];
    const float* k  = (const float*)d_in[1];
    const float* v  = (const float*)d_in[2];
    const int*   mask = (const int*)d_in[3];
    const float* Wq = (const float*)d_in[4];
    const float* Wk = (const float*)d_in[5];
    const float* Wv = (const float*)d_in[6];
    const float* Wo = (const float*)d_in[7];
    float* out = (float*)d_out;

    float *pH;
    cudaGetSymbolAddress((void**)&pH, g_H);

    static bool attr_set = false;
    if (!attr_set) {
        cudaFuncSetAttribute(attn_mma,
                             cudaFuncAttributeMaxDynamicSharedMemorySize,
                             ATTN_SMEM);
        attr_set = true;
    }

    // Split + transpose QKV weights to bf16 hi/lo planes
    w_prep<<<(3 * 512 * 512) / 256, 256>>>(Wq, Wk, Wv);

    // QKV projections: bf16x3 tensor-core GEMM, outputs pre-rounded tf32
    qkv_bf<<<dim3(BN_TOT / 128, DIN / 128, 3), 256>>>(q, k, v);

    // Pack mask to permuted bitmasks
    pack_mask<<<(BN_TOT * (NK / 64)) / 8, 256>>>(mask);

    // Flash attention (raw mma.sync tf32, register softmax, HW EX2)
    attn_mma<<<dim3(NQ / 128, BATCH, NHEADS), 256, ATTN_SMEM>>>();

    // Output projection: raw mma.sync tf32
    out_proj3<<<dim3(BN_TOT / 128, DIN / 128), 256>>>(pH, Wo, out);
}

// round 14
// speedup vs baseline: 2.5258x; 1.0391x over previous
#include <cuda_runtime.h>
#include <cuda_bf16.h>
#include <cstdint>

// Problem constants
#define BATCH   16
#define NQ      1024
#define NK      1024
#define DIN     512
#define NHEADS  8
#define HDIM    64
#define BN_TOT  (BATCH * NQ)       // 16384
#define NORM_F  0.125f             // 1/sqrt(64)
#define LOG2E   1.4426950408889634f

// -------- scratch (device globals: allocation-free) --------
// g_Q holds Q pre-scaled by NORM*LOG2E and tf32-rounded; g_K/g_V tf32-rounded.
__device__ float g_Q[(size_t)NHEADS * BN_TOT * HDIM];   // [h][bn][64]
__device__ float g_K[(size_t)NHEADS * BN_TOT * HDIM];
__device__ float g_V[(size_t)NHEADS * BN_TOT * HDIM];
__device__ float g_H[(size_t)BN_TOT * DIN];             // [bn][h*64+v], tf32-rounded
__device__ unsigned long long g_Mb[(size_t)BN_TOT * (NK / 64)];  // permuted mask bits
// bf16 hi/lo split of QKV weights, layout [op][n_global(512)][k(512)]
__device__ __nv_bfloat16 g_Wbh[(size_t)3 * 512 * 512];
__device__ __nv_bfloat16 g_Wbl[(size_t)3 * 512 * 512];

__device__ __forceinline__ float f2tf32_rna(float x) {
    uint32_t r;
    asm("cvt.rna.tf32.f32 %0, %1;" : "=r"(r) : "f"(x));
    return __uint_as_float(r);
}

__device__ __forceinline__ float ex2_approx(float x) {
    float r;
    asm("ex2.approx.f32 %0, %1;" : "=f"(r) : "f"(x));
    return r;
}

__device__ __forceinline__ uint32_t smem_u32(const void* p) {
    uint32_t a;
    asm("{ .reg .u64 t; cvta.to.shared.u64 t, %1; cvt.u32.u64 %0, t; }"
        : "=r"(a) : "l"(p));
    return a;
}

#define CP_ASYNC16(dst_u32, src_ptr) \
    asm volatile("cp.async.cg.shared.global [%0], [%1], 16;" \
                 :: "r"(dst_u32), "l"(src_ptr) : "memory")
#define CP_COMMIT() asm volatile("cp.async.commit_group;" ::: "memory")

// m16n8k8 tf32 mma (g=lane>>2, t=lane&3):
//   A: a0(g,t) a1(g+8,t) a2(g,t+4) a3(g+8,t+4)
//   B: b0(k=t,n=g) b1(k=t+4,n=g)
//   C: c0(g,2t) c1(g,2t+1) c2(g+8,2t) c3(g+8,2t+1)
__device__ __forceinline__ void mma_tf32(float* c, const uint32_t* a, const uint32_t* b) {
    asm volatile(
        "mma.sync.aligned.m16n8k8.row.col.f32.tf32.tf32.f32 "
        "{%0,%1,%2,%3}, {%4,%5,%6,%7}, {%8,%9}, {%0,%1,%2,%3};"
        : "+f"(c[0]), "+f"(c[1]), "+f"(c[2]), "+f"(c[3])
        : "r"(a[0]), "r"(a[1]), "r"(a[2]), "r"(a[3]), "r"(b[0]), "r"(b[1]));
}

// m16n8k16 bf16 mma. Each 32-bit reg = 2 bf16 along K.
__device__ __forceinline__ void mma_bf16(float* c, const uint32_t* a,
                                         uint32_t b0, uint32_t b1) {
    asm volatile(
        "mma.sync.aligned.m16n8k16.row.col.f32.bf16.bf16.f32 "
        "{%0,%1,%2,%3}, {%4,%5,%6,%7}, {%8,%9}, {%0,%1,%2,%3};"
        : "+f"(c[0]), "+f"(c[1]), "+f"(c[2]), "+f"(c[3])
        : "r"(a[0]), "r"(a[1]), "r"(a[2]), "r"(a[3]), "r"(b0), "r"(b1));
}

// ============================================================
// W prep: split QKV weights to bf16 hi/lo, transposed to [op][n][k].
// ============================================================
__global__ __launch_bounds__(256)
void w_prep(const float* __restrict__ Wq,
            const float* __restrict__ Wk,
            const float* __restrict__ Wv)
{
    size_t idx = (size_t)blockIdx.x * 256 + threadIdx.x;   // [op][n][k]
    int k  = idx & 511;
    int n  = (idx >> 9) & 511;
    int op = (int)(idx >> 18);
    const float* W = (op == 0 ? Wq : (op == 1 ? Wk : Wv));
    float w = W[(size_t)((n >> 6) * 512 + k) * 64 + (n & 63)];
    __nv_bfloat16 hi = __float2bfloat16_rn(w);
    __nv_bfloat16 lo = __float2bfloat16_rn(w - __bfloat162float(hi));
    g_Wbh[idx] = hi;
    g_Wbl[idx] = lo;
}

// ============================================================
// QKV projection via bf16x3 split tensor-core GEMM (R13 — measured good).
// ============================================================
#define QLD 40

__global__ __launch_bounds__(256, 2)
void qkv_bf(const float* __restrict__ q,
            const float* __restrict__ k,
            const float* __restrict__ v)
{
    __shared__ __nv_bfloat16 sAh[128 * QLD];
    __shared__ __nv_bfloat16 sAl[128 * QLD];
    __shared__ __nv_bfloat16 sWh[128 * QLD];
    __shared__ __nv_bfloat16 sWl[128 * QLD];

    const int tid  = threadIdx.x;
    const int w    = tid >> 5;
    const int lane = tid & 31;
    const int g    = lane >> 2;
    const int t    = lane & 3;
    const int wm   = w & 3;
    const int wn   = w >> 2;
    const int op   = blockIdx.z;
    const int m0   = blockIdx.x * 128;
    const int n0   = blockIdx.y * 128;

    const float* X = (op == 0 ? q : (op == 1 ? k : v));
    float* Cb      = (op == 0 ? g_Q : (op == 1 ? g_K : g_V));
    const __nv_bfloat16* Wh = g_Wbh + ((size_t)op * 512 + n0) * 512;
    const __nv_bfloat16* Wl = g_Wbl + ((size_t)op * 512 + n0) * 512;

    float acc[2][8][4];
#pragma unroll
    for (int mi = 0; mi < 2; ++mi)
#pragma unroll
        for (int nf = 0; nf < 8; ++nf)
#pragma unroll
            for (int j = 0; j < 4; ++j) acc[mi][nf][j] = 0.f;

    for (int c = 0; c < DIN / 32; ++c) {
        const int k0 = c * 32;
        if (c > 0) __syncthreads();

#pragma unroll
        for (int i = 0; i < 4; ++i) {
            int idx = tid + i * 256;
            int m  = idx >> 3;
            int kg = idx & 7;
            float4 xv = *(const float4*)(X + (size_t)(m0 + m) * DIN + k0 + kg * 4);
            union { __nv_bfloat16 b[4]; uint2 u; } uh, ul;
            float vv[4] = {xv.x, xv.y, xv.z, xv.w};
#pragma unroll
            for (int j = 0; j < 4; ++j) {
                __nv_bfloat16 hb = __float2bfloat16_rn(vv[j]);
                uh.b[j] = hb;
                ul.b[j] = __float2bfloat16_rn(vv[j] - __bfloat162float(hb));
            }
            *(uint2*)(sAh + m * QLD + kg * 4) = uh.u;
            *(uint2*)(sAl + m * QLD + kg * 4) = ul.u;
        }
#pragma unroll
        for (int i = 0; i < 2; ++i) {
            int s  = tid + i * 256;
            int n  = s >> 2;
            int kg = s & 3;
            *(uint4*)(sWh + n * QLD + kg * 8) =
                *(const uint4*)(Wh + (size_t)n * 512 + k0 + kg * 8);
            *(uint4*)(sWl + n * QLD + kg * 8) =
                *(const uint4*)(Wl + (size_t)n * 512 + k0 + kg * 8);
        }
        __syncthreads();

#pragma unroll
        for (int kc2 = 0; kc2 < 2; ++kc2) {
            const int kb = kc2 * 16;
            uint32_t ah[2][4], al[2][4];
#pragma unroll
            for (int mi = 0; mi < 2; ++mi) {
                int r0 = wm * 32 + mi * 16 + g;
                int r1 = r0 + 8;
                ah[mi][0] = *(const uint32_t*)(sAh + r0 * QLD + kb + 2 * t);
                ah[mi][1] = *(const uint32_t*)(sAh + r1 * QLD + kb + 2 * t);
                ah[mi][2] = *(const uint32_t*)(sAh + r0 * QLD + kb + 8 + 2 * t);
                ah[mi][3] = *(const uint32_t*)(sAh + r1 * QLD + kb + 8 + 2 * t);
                al[mi][0] = *(const uint32_t*)(sAl + r0 * QLD + kb + 2 * t);
                al[mi][1] = *(const uint32_t*)(sAl + r1 * QLD + kb + 2 * t);
                al[mi][2] = *(const uint32_t*)(sAl + r0 * QLD + kb + 8 + 2 * t);
                al[mi][3] = *(const uint32_t*)(sAl + r1 * QLD + kb + 8 + 2 * t);
            }
#pragma unroll
            for (int nf = 0; nf < 8; ++nf) {
                int col = wn * 64 + nf * 8 + g;
                uint32_t bh0 = *(const uint32_t*)(sWh + col * QLD + kb + 2 * t);
                uint32_t bh1 = *(const uint32_t*)(sWh + col * QLD + kb + 8 + 2 * t);
                uint32_t bl0 = *(const uint32_t*)(sWl + col * QLD + kb + 2 * t);
                uint32_t bl1 = *(const uint32_t*)(sWl + col * QLD + kb + 8 + 2 * t);
                mma_bf16(acc[0][nf], ah[0], bh0, bh1);   // hi*hi
                mma_bf16(acc[1][nf], ah[1], bh0, bh1);
                mma_bf16(acc[0][nf], ah[0], bl0, bl1);   // hi*lo
                mma_bf16(acc[1][nf], ah[1], bl0, bl1);
                mma_bf16(acc[0][nf], al[0], bh0, bh1);   // lo*hi
                mma_bf16(acc[1][nf], al[1], bh0, bh1);
            }
        }
    }

    const float osc = (op == 0) ? (NORM_F * LOG2E) : 1.0f;
    const int hb = (n0 >> 6) + wn;
#pragma unroll
    for (int mi = 0; mi < 2; ++mi) {
        int r0 = m0 + wm * 32 + mi * 16 + g;
        float* o0 = Cb + ((size_t)hb * BN_TOT + r0) * HDIM;
        float* o1 = Cb + ((size_t)hb * BN_TOT + r0 + 8) * HDIM;
#pragma unroll
        for (int nf = 0; nf < 8; ++nf) {
            *(float2*)(o0 + nf * 8 + 2 * t) =
                make_float2(f2tf32_rna(acc[mi][nf][0] * osc), f2tf32_rna(acc[mi][nf][1] * osc));
            *(float2*)(o1 + nf * 8 + 2 * t) =
                make_float2(f2tf32_rna(acc[mi][nf][2] * osc), f2tf32_rna(acc[mi][nf][3] * osc));
        }
    }
}

// ============================================================
// Mask pack, PERMUTED layout (R13 — measured good).
// ============================================================
__global__ __launch_bounds__(256)
void pack_mask(const int* __restrict__ mask)
{
    int w = (blockIdx.x * 256 + threadIdx.x) >> 5;
    int L = threadIdx.x & 31;
    const int* src = mask + (size_t)w * 64;
    int t_lo = L >> 4;
    int nt   = (L >> 1) & 7;
    int par  = L & 1;
    int c_lo = nt * 8 + 2 * t_lo + par;
    int c_hi = nt * 8 + 2 * (t_lo + 2) + par;
    unsigned lo = __ballot_sync(0xffffffffu, src[c_lo] != 0);
    unsigned hi = __ballot_sync(0xffffffffu, src[c_hi] != 0);
    if (L == 0)
        g_Mb[w] = ((unsigned long long)hi << 32) | (unsigned long long)lo;
}

// ============================================================
// Out projection with RAW mma.sync tf32 (R13 — measured good).
// ============================================================
#define OP_LDH 40
#define OP_LDW 136

__global__ __launch_bounds__(256, 2)
void out_proj3(const float* __restrict__ A,
               const float* __restrict__ B,
               float* __restrict__ C)
{
    __shared__ float sH[128 * OP_LDH];
    __shared__ float sW[32 * OP_LDW];

    const int tid  = threadIdx.x;
    const int w    = tid >> 5;
    const int lane = tid & 31;
    const int g    = lane >> 2;
    const int t    = lane & 3;
    const int wm   = w & 3;
    const int wn   = w >> 2;
    const int m0   = blockIdx.x * 128;
    const int n0   = blockIdx.y * 128;

    const float* At = A + (size_t)m0 * DIN;
    const float* Bt = B + n0;
    const int c4b = tid & 31;

    float acc[2][8][4];
#pragma unroll
    for (int mi = 0; mi < 2; ++mi)
#pragma unroll
        for (int nf = 0; nf < 8; ++nf)
#pragma unroll
            for (int j = 0; j < 4; ++j) acc[mi][nf][j] = 0.f;

    float4 ar[4], br[4];
#pragma unroll
    for (int i = 0; i < 4; ++i) {
        int idx = tid + i * 256;
        ar[i] = *(const float4*)(At + (size_t)(idx >> 3) * DIN + (idx & 7) * 4);
        br[i] = *(const float4*)(Bt + (size_t)((tid >> 5) + i * 8) * DIN + c4b * 4);
    }
#pragma unroll
    for (int i = 0; i < 4; ++i) {
        int idx = tid + i * 256;
        *(float4*)(sH + (idx >> 3) * OP_LDH + (idx & 7) * 4) = ar[i];
        float4 bv = br[i];
        bv.x = f2tf32_rna(bv.x); bv.y = f2tf32_rna(bv.y);
        bv.z = f2tf32_rna(bv.z); bv.w = f2tf32_rna(bv.w);
        *(float4*)(sW + ((tid >> 5) + i * 8) * OP_LDW + c4b * 4) = bv;
    }
    __syncthreads();

    for (int c = 0; c < DIN / 32; ++c) {
        if (c < DIN / 32 - 1) {
            const int k0n = (c + 1) * 32;
#pragma unroll
            for (int i = 0; i < 4; ++i) {
                int idx = tid + i * 256;
                ar[i] = *(const float4*)(At + (size_t)(idx >> 3) * DIN + k0n + (idx & 7) * 4);
                br[i] = *(const float4*)(Bt + (size_t)(k0n + (tid >> 5) + i * 8) * DIN + c4b * 4);
            }
        }

#pragma unroll
        for (int kc = 0; kc < 4; ++kc) {
            uint32_t af[2][4];
#pragma unroll
            for (int mi = 0; mi < 2; ++mi) {
                const float* r0 = sH + (wm * 32 + mi * 16 + g) * OP_LDH + kc * 8;
                const float* r1 = sH + (wm * 32 + mi * 16 + g + 8) * OP_LDH + kc * 8;
                af[mi][0] = __float_as_uint(r0[t]);
                af[mi][1] = __float_as_uint(r1[t]);
                af[mi][2] = __float_as_uint(r0[t + 4]);
                af[mi][3] = __float_as_uint(r1[t + 4]);
            }
#pragma unroll
            for (int nf = 0; nf < 8; ++nf) {
                uint32_t bfr[2];
                bfr[0] = __float_as_uint(sW[(kc * 8 + t) * OP_LDW + wn * 64 + nf * 8 + g]);
                bfr[1] = __float_as_uint(sW[(kc * 8 + t + 4) * OP_LDW + wn * 64 + nf * 8 + g]);
                mma_tf32(acc[0][nf], af[0], bfr);
                mma_tf32(acc[1][nf], af[1], bfr);
            }
        }
        __syncthreads();

        if (c < DIN / 32 - 1) {
#pragma unroll
            for (int i = 0; i < 4; ++i) {
                int idx = tid + i * 256;
                *(float4*)(sH + (idx >> 3) * OP_LDH + (idx & 7) * 4) = ar[i];
                float4 bv = br[i];
                bv.x = f2tf32_rna(bv.x); bv.y = f2tf32_rna(bv.y);
                bv.z = f2tf32_rna(bv.z); bv.w = f2tf32_rna(bv.w);
                *(float4*)(sW + ((tid >> 5) + i * 8) * OP_LDW + c4b * 4) = bv;
            }
            __syncthreads();
        }
    }

#pragma unroll
    for (int mi = 0; mi < 2; ++mi) {
        float* r0 = C + (size_t)(m0 + wm * 32 + mi * 16 + g) * DIN + n0 + wn * 64;
        float* r1 = C + (size_t)(m0 + wm * 32 + mi * 16 + g + 8) * DIN + n0 + wn * 64;
#pragma unroll
        for (int nf = 0; nf < 8; ++nf) {
            *(float2*)(r0 + nf * 8 + 2 * t) = make_float2(acc[mi][nf][0], acc[mi][nf][1]);
            *(float2*)(r1 + nf * 8 + 2 * t) = make_float2(acc[mi][nf][2], acc[mi][nf][3]);
        }
    }
}

// ============================================================
// FA2-style flash attention, raw mma.sync tf32, HW EX2.
// R14: K/V tiles double-buffered via cp.async (prefetch tile kt+1 during
// compute of tile kt). smem 104 KB/CTA -> still 2 CTAs/SM.
// ============================================================
#define LDK 68
#define LDV 72
#define LDP 68
#define SKT (64 * LDK)
#define SVT (64 * LDV)
#define ATTN_SMEM ((2 * SKT + 2 * SVT + 128 * LDP) * 4)

__global__ __launch_bounds__(256, 2)
void attn_mma()
{
    extern __shared__ float sm[];
    float* sK = sm;                   // [2][64][LDK]
    float* sV = sm + 2 * SKT;         // [2][64][LDV]
    float* sP = sm + 2 * SKT + 2 * SVT;

    const int tid  = threadIdx.x;
    const int w    = tid >> 5;
    const int lane = tid & 31;
    const int g    = lane >> 2;
    const int t    = lane & 3;
    const int q0   = blockIdx.x * 128;
    const int b    = blockIdx.y;
    const int h    = blockIdx.z;

    const float* Qg = g_Q + ((size_t)(h * BATCH + b) * NQ + q0) * HDIM;
    const float* Kg = g_K + (size_t)(h * BATCH + b) * NK * HDIM;
    const float* Vg = g_V + (size_t)(h * BATCH + b) * NK * HDIM;

    // staging pattern: idx = tid + i*256 -> row r = idx>>4, col c4 = idx&15
    const int sr  = tid >> 4;         // rows this thread covers: sr, sr+16, sr+32, sr+48
    const int sc4 = (tid & 15) * 4;
    const uint32_t sKu = smem_u32(sK);
    const uint32_t sVu = smem_u32(sV);

    // Q already scaled + tf32-rounded: raw bit loads.
    uint32_t qf[8][4];
#pragma unroll
    for (int kc = 0; kc < 8; ++kc) {
        const uint32_t* r0 = (const uint32_t*)(Qg + (size_t)(w * 16 + g) * HDIM + kc * 8);
        const uint32_t* r1 = (const uint32_t*)(Qg + (size_t)(w * 16 + g + 8) * HDIM + kc * 8);
        qf[kc][0] = r0[t];
        qf[kc][1] = r1[t];
        qf[kc][2] = r0[t + 4];
        qf[kc][3] = r1[t + 4];
    }

    float oacc[8][4];
#pragma unroll
    for (int nt = 0; nt < 8; ++nt)
#pragma unroll
        for (int j = 0; j < 4; ++j) oacc[nt][j] = 0.f;
    float m0 = -1e30f, m1 = -1e30f;
    float l0 = 0.f, l1 = 0.f;

    const unsigned long long* mb_row0 = g_Mb + ((size_t)b * NQ + q0 + w * 16 + g) * (NK / 64);
    const unsigned long long* mb_row1 = mb_row0 + 8 * (NK / 64);
    float* sPw = sP + (w * 16) * LDP;
    const int tsh = t * 16;

    // ---- prologue: issue tile 0 into buffer 0 ----
#pragma unroll
    for (int i = 0; i < 4; ++i) {
        int r = sr + i * 16;
        CP_ASYNC16(sKu + (r * LDK + sc4) * 4, Kg + (size_t)r * HDIM + sc4);
        CP_ASYNC16(sVu + (r * LDV + sc4) * 4, Vg + (size_t)r * HDIM + sc4);
    }
    CP_COMMIT();

    for (int kt = 0; kt < NK / 64; ++kt) {
        const int cur = kt & 1;
        __syncthreads();   // compute(kt-1) retired block-wide -> buf cur^1 free

        if (kt < NK / 64 - 1) {
            const int nxt = cur ^ 1;
            const float* Kn = Kg + (size_t)(kt + 1) * 64 * HDIM;
            const float* Vn = Vg + (size_t)(kt + 1) * 64 * HDIM;
#pragma unroll
            for (int i = 0; i < 4; ++i) {
                int r = sr + i * 16;
                CP_ASYNC16(sKu + (nxt * SKT + r * LDK + sc4) * 4, Kn + (size_t)r * HDIM + sc4);
                CP_ASYNC16(sVu + (nxt * SVT + r * LDV + sc4) * 4, Vn + (size_t)r * HDIM + sc4);
            }
            CP_COMMIT();
            asm volatile("cp.async.wait_group 1;" ::: "memory");   // tile kt done
        } else {
            asm volatile("cp.async.wait_group 0;" ::: "memory");
        }
        __syncthreads();   // tile kt visible to all warps

        const float* sKc = sK + cur * SKT;
        const float* sVc = sV + cur * SVT;

        float sacc[8][4];
#pragma unroll
        for (int nt = 0; nt < 8; ++nt) {
#pragma unroll
            for (int j = 0; j < 4; ++j) sacc[nt][j] = 0.f;
#pragma unroll
            for (int kc = 0; kc < 8; ++kc) {
                uint32_t bfr[2];
                const float* kb = sKc + (nt * 8 + g) * LDK + kc * 8;
                bfr[0] = __float_as_uint(kb[t]);
                bfr[1] = __float_as_uint(kb[t + 4]);
                mma_tf32(sacc[nt], qf[kc], bfr);
            }
        }

        uint32_t ch0 = (uint32_t)(mb_row0[kt] >> tsh) & 0xffffu;
        uint32_t ch1 = (uint32_t)(mb_row1[kt] >> tsh) & 0xffffu;
        float tmax0 = -1e30f, tmax1 = -1e30f;
#pragma unroll
        for (int nt = 0; nt < 8; ++nt) {
            if (ch0 & (1u << (2 * nt)))     sacc[nt][0] = -1e30f;
            if (ch0 & (2u << (2 * nt)))     sacc[nt][1] = -1e30f;
            if (ch1 & (1u << (2 * nt)))     sacc[nt][2] = -1e30f;
            if (ch1 & (2u << (2 * nt)))     sacc[nt][3] = -1e30f;
            tmax0 = fmaxf(tmax0, fmaxf(sacc[nt][0], sacc[nt][1]));
            tmax1 = fmaxf(tmax1, fmaxf(sacc[nt][2], sacc[nt][3]));
        }
        tmax0 = fmaxf(tmax0, __shfl_xor_sync(0xffffffffu, tmax0, 1));
        tmax0 = fmaxf(tmax0, __shfl_xor_sync(0xffffffffu, tmax0, 2));
        tmax1 = fmaxf(tmax1, __shfl_xor_sync(0xffffffffu, tmax1, 1));
        tmax1 = fmaxf(tmax1, __shfl_xor_sync(0xffffffffu, tmax1, 2));

        float mn0 = fmaxf(m0, tmax0);
        float mn1 = fmaxf(m1, tmax1);
        float sc0 = ex2_approx(m0 - mn0);
        float sc1 = ex2_approx(m1 - mn1);
        m0 = mn0; m1 = mn1;

        float ps0 = 0.f, ps1 = 0.f;
#pragma unroll
        for (int nt = 0; nt < 8; ++nt) {
            float p0 = ex2_approx(sacc[nt][0] - mn0);
            float p1 = ex2_approx(sacc[nt][1] - mn0);
            float p2 = ex2_approx(sacc[nt][2] - mn1);
            float p3 = ex2_approx(sacc[nt][3] - mn1);
            ps0 += p0 + p1;
            ps1 += p2 + p3;
            float2 lo = make_float2(f2tf32_rna(p0), f2tf32_rna(p1));
            float2 hi = make_float2(f2tf32_rna(p2), f2tf32_rna(p3));
            *(float2*)(sPw + g * LDP + nt * 8 + 2 * t) = lo;
            *(float2*)(sPw + (g + 8) * LDP + nt * 8 + 2 * t) = hi;
        }
        ps0 += __shfl_xor_sync(0xffffffffu, ps0, 1);
        ps0 += __shfl_xor_sync(0xffffffffu, ps0, 2);
        ps1 += __shfl_xor_sync(0xffffffffu, ps1, 1);
        ps1 += __shfl_xor_sync(0xffffffffu, ps1, 2);
        l0 = l0 * sc0 + ps0;
        l1 = l1 * sc1 + ps1;

#pragma unroll
        for (int nt = 0; nt < 8; ++nt) {
            oacc[nt][0] *= sc0; oacc[nt][1] *= sc0;
            oacc[nt][2] *= sc1; oacc[nt][3] *= sc1;
        }
        __syncwarp();

#pragma unroll
        for (int kc = 0; kc < 8; ++kc) {
            uint32_t pa[4];
            const float* p0r = sPw + g * LDP + kc * 8;
            const float* p1r = sPw + (g + 8) * LDP + kc * 8;
            pa[0] = __float_as_uint(p0r[t]);
            pa[1] = __float_as_uint(p1r[t]);
            pa[2] = __float_as_uint(p0r[t + 4]);
            pa[3] = __float_as_uint(p1r[t + 4]);
#pragma unroll
            for (int nt = 0; nt < 8; ++nt) {
                uint32_t bfr[2];
                bfr[0] = __float_as_uint(sVc[(kc * 8 + t) * LDV + nt * 8 + g]);
                bfr[1] = __float_as_uint(sVc[(kc * 8 + t + 4) * LDV + nt * 8 + g]);
                mma_tf32(oacc[nt], pa, bfr);
            }
        }
        __syncwarp();
    }

    float inv0 = (l0 > 0.f) ? (1.f / l0) : 0.f;
    float inv1 = (l1 > 0.f) ? (1.f / l1) : 0.f;
    float* o0 = g_H + ((size_t)(b * NQ + q0 + w * 16 + g)) * DIN + h * HDIM;
    float* o1 = g_H + ((size_t)(b * NQ + q0 + w * 16 + g + 8)) * DIN + h * HDIM;
#pragma unroll
    for (int nt = 0; nt < 8; ++nt) {
        *(float2*)(o0 + nt * 8 + 2 * t) =
            make_float2(f2tf32_rna(oacc[nt][0] * inv0), f2tf32_rna(oacc[nt][1] * inv0));
        *(float2*)(o1 + nt * 8 + 2 * t) =
            make_float2(f2tf32_rna(oacc[nt][2] * inv1), f2tf32_rna(oacc[nt][3] * inv1));
    }
}

// ============================================================
extern "C" void kernel_launch(void* const* d_in, const int* in_sizes, int n_in,
                              void* d_out, int out_size)
{
    const float* q  = (const float*)d_in[0];
    const float* k  = (const float*)d_in[1];
    const float* v  = (const float*)d_in[2];
    const int*   mask = (const int*)d_in[3];
    const float* Wq = (const float*)d_in[4];
    const float* Wk = (const float*)d_in[5];
    const float* Wv = (const float*)d_in[6];
    const float* Wo = (const float*)d_in[7];
    float* out = (float*)d_out;

    float *pH;
    cudaGetSymbolAddress((void**)&pH, g_H);

    static bool attr_set = false;
    if (!attr_set) {
        cudaFuncSetAttribute(attn_mma,
                             cudaFuncAttributeMaxDynamicSharedMemorySize,
                             ATTN_SMEM);
        attr_set = true;
    }

    // Split + transpose QKV weights to bf16 hi/lo planes
    w_prep<<<(3 * 512 * 512) / 256, 256>>>(Wq, Wk, Wv);

    // QKV projections: bf16x3 tensor-core GEMM, outputs pre-rounded tf32
    qkv_bf<<<dim3(BN_TOT / 128, DIN / 128, 3), 256>>>(q, k, v);

    // Pack mask to permuted bitmasks
    pack_mask<<<(BN_TOT * (NK / 64)) / 8, 256>>>(mask);

    // Flash attention (raw mma.sync tf32, cp.async double-buffered K/V)
    attn_mma<<<dim3(NQ / 128, BATCH, NHEADS), 256, ATTN_SMEM>>>();

    // Output projection: raw mma.sync tf32
    out_proj3<<<dim3(BN_TOT / 128, DIN / 128), 256>>>(pH, Wo, out);
}